// round 1
// baseline (speedup 1.0000x reference)
#include <cuda_runtime.h>
#include <math.h>

#define N_ROWS 4096
#define DIM    1024
#define H1     512
#define H2     256
#define LAT    128
#define SLOPE  0.01f

// -------- scratch (no allocations allowed) --------
__device__ float g_h1[N_ROWS * H1];
__device__ float g_h2[N_ROWS * H2];
__device__ float g_lat[N_ROWS * LAT];
__device__ float g_d1[N_ROWS * H2];
__device__ float g_d2[N_ROWS * H1];
__device__ float g_rx[N_ROWS];
__device__ float g_rl[N_ROWS];
__device__ double g_stats[5];   // s1, s2, s11, s22, s12

__global__ void zero_stats_kernel() {
    if (threadIdx.x < 5) g_stats[threadIdx.x] = 0.0;
}

// -------- fused GEMM + bias + LeakyReLU --------
// C[m,n] = lrelu( sum_k A[m,k] * W[n,k] + b[n] )
// Tile 64x64, 256 threads, 4x4 per thread, K-chunk 16.
// Requires M%64==0, N%64==0, K%16==0 (true for all 6 layers).
__global__ void gemm_bias_lrelu_kernel(const float* __restrict__ A,
                                       const float* __restrict__ W,
                                       const float* __restrict__ bias,
                                       float* __restrict__ C,
                                       int M, int N, int K) {
    __shared__ float As[16][65];
    __shared__ float Ws[16][65];

    const int t  = threadIdx.x;          // 0..255
    const int tx = t & 15;
    const int ty = t >> 4;
    const int m0 = blockIdx.y * 64;
    const int n0 = blockIdx.x * 64;

    const int lrow = t >> 2;             // 0..63
    const int lcol = (t & 3) * 4;        // 0,4,8,12
    const float* Ap = A + (size_t)(m0 + lrow) * K + lcol;
    const float* Wp = W + (size_t)(n0 + lrow) * K + lcol;

    float acc[4][4];
#pragma unroll
    for (int i = 0; i < 4; i++)
#pragma unroll
        for (int j = 0; j < 4; j++) acc[i][j] = 0.f;

    for (int k0 = 0; k0 < K; k0 += 16) {
        float4 va = *(const float4*)(Ap + k0);
        float4 vw = *(const float4*)(Wp + k0);
        As[lcol + 0][lrow] = va.x; As[lcol + 1][lrow] = va.y;
        As[lcol + 2][lrow] = va.z; As[lcol + 3][lrow] = va.w;
        Ws[lcol + 0][lrow] = vw.x; Ws[lcol + 1][lrow] = vw.y;
        Ws[lcol + 2][lrow] = vw.z; Ws[lcol + 3][lrow] = vw.w;
        __syncthreads();
#pragma unroll
        for (int kk = 0; kk < 16; kk++) {
            float a0 = As[kk][ty * 4 + 0], a1 = As[kk][ty * 4 + 1];
            float a2 = As[kk][ty * 4 + 2], a3 = As[kk][ty * 4 + 3];
            float w0 = Ws[kk][tx * 4 + 0], w1 = Ws[kk][tx * 4 + 1];
            float w2 = Ws[kk][tx * 4 + 2], w3 = Ws[kk][tx * 4 + 3];
            acc[0][0] += a0 * w0; acc[0][1] += a0 * w1; acc[0][2] += a0 * w2; acc[0][3] += a0 * w3;
            acc[1][0] += a1 * w0; acc[1][1] += a1 * w1; acc[1][2] += a1 * w2; acc[1][3] += a1 * w3;
            acc[2][0] += a2 * w0; acc[2][1] += a2 * w1; acc[2][2] += a2 * w2; acc[2][3] += a2 * w3;
            acc[3][0] += a3 * w0; acc[3][1] += a3 * w1; acc[3][2] += a3 * w2; acc[3][3] += a3 * w3;
        }
        __syncthreads();
    }

#pragma unroll
    for (int i = 0; i < 4; i++) {
        int m = m0 + ty * 4 + i;
#pragma unroll
        for (int j = 0; j < 4; j++) {
            int n = n0 + tx * 4 + j;
            float v = acc[i][j] + bias[n];
            C[(size_t)m * N + n] = (v >= 0.f) ? v : SLOPE * v;
        }
    }
}

// -------- row squared-norms --------
__global__ void rownorm_kernel(const float* __restrict__ X, float* __restrict__ r, int K) {
    int row = blockIdx.x;
    const float* p = X + (size_t)row * K;
    float s = 0.f;
    for (int k = threadIdx.x; k < K; k += blockDim.x) {
        float v = p[k];
        s += v * v;
    }
#pragma unroll
    for (int off = 16; off > 0; off >>= 1)
        s += __shfl_down_sync(0xffffffffu, s, off);
    __shared__ float sm[32];
    int lane = threadIdx.x & 31, wid = threadIdx.x >> 5;
    if (lane == 0) sm[wid] = s;
    __syncthreads();
    if (wid == 0) {
        int nw = blockDim.x >> 5;
        float v = (lane < nw) ? sm[lane] : 0.f;
#pragma unroll
        for (int off = 16; off > 0; off >>= 1)
            v += __shfl_down_sync(0xffffffffu, v, off);
        if (lane == 0) r[row] = v;
    }
}

// -------- fused pairwise-distance + correlation stats --------
// One 64x64 (i,j)-tile per block; upper triangle only (symmetry, weight 2).
// Computes Gram tiles for x (K=1024) and latent (K=128), converts to distances,
// accumulates 5 double sums via block reduction + atomicAdd.
__global__ void dist_stats_kernel(const float* __restrict__ X,
                                  const float* __restrict__ Lt,
                                  const float* __restrict__ rx,
                                  const float* __restrict__ rl) {
    const int bi = blockIdx.y, bj = blockIdx.x;
    if (bj < bi) return;

    __shared__ float As[16][65];
    __shared__ float Bs[16][65];
    __shared__ double red[256];

    const int t  = threadIdx.x;
    const int tx = t & 15;
    const int ty = t >> 4;
    const int i0 = bi * 64;
    const int j0 = bj * 64;
    const int lrow = t >> 2;
    const int lcol = (t & 3) * 4;

    float accx[4][4], accl[4][4];
#pragma unroll
    for (int i = 0; i < 4; i++)
#pragma unroll
        for (int j = 0; j < 4; j++) { accx[i][j] = 0.f; accl[i][j] = 0.f; }

    // Gram for x, K = 1024
    {
        const float* Ap = X + (size_t)(i0 + lrow) * DIM + lcol;
        const float* Bp = X + (size_t)(j0 + lrow) * DIM + lcol;
        for (int k0 = 0; k0 < DIM; k0 += 16) {
            float4 va = *(const float4*)(Ap + k0);
            float4 vb = *(const float4*)(Bp + k0);
            As[lcol + 0][lrow] = va.x; As[lcol + 1][lrow] = va.y;
            As[lcol + 2][lrow] = va.z; As[lcol + 3][lrow] = va.w;
            Bs[lcol + 0][lrow] = vb.x; Bs[lcol + 1][lrow] = vb.y;
            Bs[lcol + 2][lrow] = vb.z; Bs[lcol + 3][lrow] = vb.w;
            __syncthreads();
#pragma unroll
            for (int kk = 0; kk < 16; kk++) {
                float a0 = As[kk][ty * 4 + 0], a1 = As[kk][ty * 4 + 1];
                float a2 = As[kk][ty * 4 + 2], a3 = As[kk][ty * 4 + 3];
                float b0 = Bs[kk][tx * 4 + 0], b1 = Bs[kk][tx * 4 + 1];
                float b2 = Bs[kk][tx * 4 + 2], b3 = Bs[kk][tx * 4 + 3];
                accx[0][0] += a0 * b0; accx[0][1] += a0 * b1; accx[0][2] += a0 * b2; accx[0][3] += a0 * b3;
                accx[1][0] += a1 * b0; accx[1][1] += a1 * b1; accx[1][2] += a1 * b2; accx[1][3] += a1 * b3;
                accx[2][0] += a2 * b0; accx[2][1] += a2 * b1; accx[2][2] += a2 * b2; accx[2][3] += a2 * b3;
                accx[3][0] += a3 * b0; accx[3][1] += a3 * b1; accx[3][2] += a3 * b2; accx[3][3] += a3 * b3;
            }
            __syncthreads();
        }
    }
    // Gram for latent, K = 128
    {
        const float* Ap = Lt + (size_t)(i0 + lrow) * LAT + lcol;
        const float* Bp = Lt + (size_t)(j0 + lrow) * LAT + lcol;
        for (int k0 = 0; k0 < LAT; k0 += 16) {
            float4 va = *(const float4*)(Ap + k0);
            float4 vb = *(const float4*)(Bp + k0);
            As[lcol + 0][lrow] = va.x; As[lcol + 1][lrow] = va.y;
            As[lcol + 2][lrow] = va.z; As[lcol + 3][lrow] = va.w;
            Bs[lcol + 0][lrow] = vb.x; Bs[lcol + 1][lrow] = vb.y;
            Bs[lcol + 2][lrow] = vb.z; Bs[lcol + 3][lrow] = vb.w;
            __syncthreads();
#pragma unroll
            for (int kk = 0; kk < 16; kk++) {
                float a0 = As[kk][ty * 4 + 0], a1 = As[kk][ty * 4 + 1];
                float a2 = As[kk][ty * 4 + 2], a3 = As[kk][ty * 4 + 3];
                float b0 = Bs[kk][tx * 4 + 0], b1 = Bs[kk][tx * 4 + 1];
                float b2 = Bs[kk][tx * 4 + 2], b3 = Bs[kk][tx * 4 + 3];
                accl[0][0] += a0 * b0; accl[0][1] += a0 * b1; accl[0][2] += a0 * b2; accl[0][3] += a0 * b3;
                accl[1][0] += a1 * b0; accl[1][1] += a1 * b1; accl[1][2] += a1 * b2; accl[1][3] += a1 * b3;
                accl[2][0] += a2 * b0; accl[2][1] += a2 * b1; accl[2][2] += a2 * b2; accl[2][3] += a2 * b3;
                accl[3][0] += a3 * b0; accl[3][1] += a3 * b1; accl[3][2] += a3 * b2; accl[3][3] += a3 * b3;
            }
            __syncthreads();
        }
    }

    // distances + stats (weight 2 for j>i, 0 otherwise; diagonal d=0)
    double s1 = 0.0, s2 = 0.0, s11 = 0.0, s22 = 0.0, s12 = 0.0;
#pragma unroll
    for (int ii = 0; ii < 4; ii++) {
        int i = i0 + ty * 4 + ii;
        float rxi = rx[i], rli = rl[i];
#pragma unroll
        for (int jj = 0; jj < 4; jj++) {
            int j = j0 + tx * 4 + jj;
            if (j > i) {
                float sqx = rxi + rx[j] - 2.f * accx[ii][jj];
                float sql = rli + rl[j] - 2.f * accl[ii][jj];
                float dx = sqrtf(fmaxf(sqx, 0.f));
                float dl = sqrtf(fmaxf(sql, 0.f));
                double ddx = (double)dx, ddl = (double)dl;
                s1  += 2.0 * ddx;
                s2  += 2.0 * ddl;
                s11 += 2.0 * ddx * ddx;
                s22 += 2.0 * ddl * ddl;
                s12 += 2.0 * ddx * ddl;
            }
        }
    }

    double vals[5] = {s1, s2, s11, s22, s12};
#pragma unroll
    for (int v = 0; v < 5; v++) {
        red[t] = vals[v];
        __syncthreads();
        for (int off = 128; off > 0; off >>= 1) {
            if (t < off) red[t] += red[t + off];
            __syncthreads();
        }
        if (t == 0) atomicAdd(&g_stats[v], red[0]);
        __syncthreads();
    }
}

__global__ void finalize_kernel(float* __restrict__ out, long long idx) {
    const double n = (double)N_ROWS * (double)N_ROWS;
    double m1 = g_stats[0] / n;
    double m2 = g_stats[1] / n;
    double v1 = (g_stats[2] - n * m1 * m1) / (n - 1.0);
    double v2 = (g_stats[3] - n * m2 * m2) / (n - 1.0);
    double cov = g_stats[4] / n - m1 * m2;
    out[idx] = (float)(cov / sqrt(v1 * v2));
}

extern "C" void kernel_launch(void* const* d_in, const int* in_sizes, int n_in,
                              void* d_out, int out_size) {
    const float* x   = (const float*)d_in[0];
    const float* We1 = (const float*)d_in[1];
    const float* be1 = (const float*)d_in[2];
    const float* We2 = (const float*)d_in[3];
    const float* be2 = (const float*)d_in[4];
    const float* We3 = (const float*)d_in[5];
    const float* be3 = (const float*)d_in[6];
    const float* Wd1 = (const float*)d_in[7];
    const float* bd1 = (const float*)d_in[8];
    const float* Wd2 = (const float*)d_in[9];
    const float* bd2 = (const float*)d_in[10];
    const float* Wd3 = (const float*)d_in[11];
    const float* bd3 = (const float*)d_in[12];
    float* out = (float*)d_out;

    float* h1  = nullptr; cudaGetSymbolAddress((void**)&h1,  g_h1);
    float* h2  = nullptr; cudaGetSymbolAddress((void**)&h2,  g_h2);
    float* lat = nullptr; cudaGetSymbolAddress((void**)&lat, g_lat);
    float* dd1 = nullptr; cudaGetSymbolAddress((void**)&dd1, g_d1);
    float* dd2 = nullptr; cudaGetSymbolAddress((void**)&dd2, g_d2);
    float* rx  = nullptr; cudaGetSymbolAddress((void**)&rx,  g_rx);
    float* rl  = nullptr; cudaGetSymbolAddress((void**)&rl,  g_rl);

    zero_stats_kernel<<<1, 32>>>();

    // MLP chain (bias + LeakyReLU fused)
    gemm_bias_lrelu_kernel<<<dim3(H1 / 64,  N_ROWS / 64), 256>>>(x,   We1, be1, h1,  N_ROWS, H1,  DIM);
    gemm_bias_lrelu_kernel<<<dim3(H2 / 64,  N_ROWS / 64), 256>>>(h1,  We2, be2, h2,  N_ROWS, H2,  H1);
    gemm_bias_lrelu_kernel<<<dim3(LAT / 64, N_ROWS / 64), 256>>>(h2,  We3, be3, lat, N_ROWS, LAT, H2);
    gemm_bias_lrelu_kernel<<<dim3(H2 / 64,  N_ROWS / 64), 256>>>(lat, Wd1, bd1, dd1, N_ROWS, H2,  LAT);
    gemm_bias_lrelu_kernel<<<dim3(H1 / 64,  N_ROWS / 64), 256>>>(dd1, Wd2, bd2, dd2, N_ROWS, H1,  H2);
    gemm_bias_lrelu_kernel<<<dim3(DIM / 64, N_ROWS / 64), 256>>>(dd2, Wd3, bd3, out, N_ROWS, DIM, H1);

    // row squared norms
    rownorm_kernel<<<N_ROWS, 256>>>(x, rx, DIM);
    rownorm_kernel<<<N_ROWS, 128>>>(lat, rl, LAT);

    // fused pairwise-distance + correlation stats (upper triangle)
    dist_stats_kernel<<<dim3(N_ROWS / 64, N_ROWS / 64), 256>>>(x, lat, rx, rl);

    // corr -> last output element
    finalize_kernel<<<1, 1>>>(out, (long long)out_size - 1);
}

// round 2
// speedup vs baseline: 1.1762x; 1.1762x over previous
#include <cuda_runtime.h>
#include <math.h>

#define N_ROWS 4096
#define DIM    1024
#define H1     512
#define H2     256
#define LAT    128
#define SLOPE  0.01f
#define NB     (N_ROWS / 128)   /* 32 tile rows for dist kernel */

// -------- scratch (no allocations allowed) --------
__device__ float g_h1[N_ROWS * H1];
__device__ float g_h2[N_ROWS * H2];
__device__ float g_lat[N_ROWS * LAT];
__device__ float g_d1[N_ROWS * H2];
__device__ float g_d2[N_ROWS * H1];
__device__ float g_rx[N_ROWS];
__device__ float g_rl[N_ROWS];
__device__ double g_stats[5];   // s1, s2, s11, s22, s12 (half-sums; x2 in finalize)

__global__ void zero_stats_kernel() {
    if (threadIdx.x < 5) g_stats[threadIdx.x] = 0.0;
}

// ---- packed fp32x2 helpers (sm_103a FFMA2 path) ----
#define FMA2(d, a, b) \
    asm("fma.rn.f32x2 %0, %1, %2, %0;" : "+l"(d) : "l"(a), "l"(b))
#define PACKDUP(d, f) do { \
    unsigned _u = __float_as_uint(f); \
    asm("mov.b64 %0, {%1, %1};" : "=l"(d) : "r"(_u)); \
} while (0)
#define UNPACK2(lo, hi, v) do { \
    unsigned _l, _h; \
    asm("mov.b64 {%0, %1}, %2;" : "=r"(_l), "=r"(_h) : "l"(v)); \
    lo = __uint_as_float(_l); hi = __uint_as_float(_h); \
} while (0)

// -------- fused GEMM + bias + LeakyReLU (MLP chain; ~70us total, kept as-is) --------
__global__ void gemm_bias_lrelu_kernel(const float* __restrict__ A,
                                       const float* __restrict__ W,
                                       const float* __restrict__ bias,
                                       float* __restrict__ C,
                                       int M, int N, int K) {
    __shared__ float As[16][65];
    __shared__ float Ws[16][65];

    const int t  = threadIdx.x;
    const int tx = t & 15;
    const int ty = t >> 4;
    const int m0 = blockIdx.y * 64;
    const int n0 = blockIdx.x * 64;

    const int lrow = t >> 2;
    const int lcol = (t & 3) * 4;
    const float* Ap = A + (size_t)(m0 + lrow) * K + lcol;
    const float* Wp = W + (size_t)(n0 + lrow) * K + lcol;

    float acc[4][4];
#pragma unroll
    for (int i = 0; i < 4; i++)
#pragma unroll
        for (int j = 0; j < 4; j++) acc[i][j] = 0.f;

    for (int k0 = 0; k0 < K; k0 += 16) {
        float4 va = *(const float4*)(Ap + k0);
        float4 vw = *(const float4*)(Wp + k0);
        As[lcol + 0][lrow] = va.x; As[lcol + 1][lrow] = va.y;
        As[lcol + 2][lrow] = va.z; As[lcol + 3][lrow] = va.w;
        Ws[lcol + 0][lrow] = vw.x; Ws[lcol + 1][lrow] = vw.y;
        Ws[lcol + 2][lrow] = vw.z; Ws[lcol + 3][lrow] = vw.w;
        __syncthreads();
#pragma unroll
        for (int kk = 0; kk < 16; kk++) {
            float a0 = As[kk][ty * 4 + 0], a1 = As[kk][ty * 4 + 1];
            float a2 = As[kk][ty * 4 + 2], a3 = As[kk][ty * 4 + 3];
            float w0 = Ws[kk][tx * 4 + 0], w1 = Ws[kk][tx * 4 + 1];
            float w2 = Ws[kk][tx * 4 + 2], w3 = Ws[kk][tx * 4 + 3];
            acc[0][0] += a0 * w0; acc[0][1] += a0 * w1; acc[0][2] += a0 * w2; acc[0][3] += a0 * w3;
            acc[1][0] += a1 * w0; acc[1][1] += a1 * w1; acc[1][2] += a1 * w2; acc[1][3] += a1 * w3;
            acc[2][0] += a2 * w0; acc[2][1] += a2 * w1; acc[2][2] += a2 * w2; acc[2][3] += a2 * w3;
            acc[3][0] += a3 * w0; acc[3][1] += a3 * w1; acc[3][2] += a3 * w2; acc[3][3] += a3 * w3;
        }
        __syncthreads();
    }

#pragma unroll
    for (int i = 0; i < 4; i++) {
        int m = m0 + ty * 4 + i;
#pragma unroll
        for (int j = 0; j < 4; j++) {
            int n = n0 + tx * 4 + j;
            float v = acc[i][j] + bias[n];
            C[(size_t)m * N + n] = (v >= 0.f) ? v : SLOPE * v;
        }
    }
}

// -------- row squared-norms --------
__global__ void rownorm_kernel(const float* __restrict__ X, float* __restrict__ r, int K) {
    int row = blockIdx.x;
    const float* p = X + (size_t)row * K;
    float s = 0.f;
    for (int k = threadIdx.x; k < K; k += blockDim.x) {
        float v = p[k];
        s += v * v;
    }
#pragma unroll
    for (int off = 16; off > 0; off >>= 1)
        s += __shfl_down_sync(0xffffffffu, s, off);
    __shared__ float sm[32];
    int lane = threadIdx.x & 31, wid = threadIdx.x >> 5;
    if (lane == 0) sm[wid] = s;
    __syncthreads();
    if (wid == 0) {
        int nw = blockDim.x >> 5;
        float v = (lane < nw) ? sm[lane] : 0.f;
#pragma unroll
        for (int off = 16; off > 0; off >>= 1)
            v += __shfl_down_sync(0xffffffffu, v, off);
        if (lane == 0) r[row] = v;
    }
}

// -------- fused pairwise-distance + correlation stats, v2 --------
// 128x128 tile per block, 256 threads, 8x8 per thread via packed f32x2 FMA.
// Upper-triangle launch (528 blocks). Double-buffered smem, one sync/chunk.

#define LOADCHUNK(Pp, r0, r1, koff) do { \
    r0 = *(const float4*)(Pp + (koff) + lk); \
    r1 = *(const float4*)(Pp + (koff) + lk + 8); \
} while (0)

#define STORECHUNK(S, r0, r1) do { \
    S[lk + 0][lrow] = r0.x; S[lk + 1][lrow] = r0.y; \
    S[lk + 2][lrow] = r0.z; S[lk + 3][lrow] = r0.w; \
    S[lk + 8][lrow] = r1.x; S[lk + 9][lrow] = r1.y; \
    S[lk +10][lrow] = r1.z; S[lk +11][lrow] = r1.w; \
} while (0)

#define COMPUTE_CHUNK(SA, SB) do { \
    _Pragma("unroll") \
    for (int kk = 0; kk < 16; kk++) { \
        float4 a0 = *(const float4*)&SA[kk][ty8]; \
        float4 a1 = *(const float4*)&SA[kk][ty8 + 4]; \
        ulonglong2 b0 = *(const ulonglong2*)&SB[kk][tx8]; \
        ulonglong2 b1 = *(const ulonglong2*)&SB[kk][tx8 + 4]; \
        unsigned long long ad[8]; \
        PACKDUP(ad[0], a0.x); PACKDUP(ad[1], a0.y); \
        PACKDUP(ad[2], a0.z); PACKDUP(ad[3], a0.w); \
        PACKDUP(ad[4], a1.x); PACKDUP(ad[5], a1.y); \
        PACKDUP(ad[6], a1.z); PACKDUP(ad[7], a1.w); \
        _Pragma("unroll") \
        for (int i = 0; i < 8; i++) { \
            FMA2(acc[i][0], ad[i], b0.x); \
            FMA2(acc[i][1], ad[i], b0.y); \
            FMA2(acc[i][2], ad[i], b1.x); \
            FMA2(acc[i][3], ad[i], b1.y); \
        } \
    } \
} while (0)

__global__ void __launch_bounds__(256)
dist_stats_kernel(const float* __restrict__ X,
                  const float* __restrict__ Lt,
                  const float* __restrict__ rx,
                  const float* __restrict__ rl) {
    // decode upper-triangle block index -> (bi, bj), bi <= bj
    int b = blockIdx.x;
    int bi = 0, rem = b;
    while (rem >= NB - bi) { rem -= NB - bi; bi++; }
    int bj = bi + rem;
    const bool diag = (bi == bj);

    __shared__ __align__(16) float As[2][16][128];
    __shared__ __align__(16) float Bs[2][16][128];
    __shared__ double red[256];

    const int t    = threadIdx.x;
    const int tx8  = (t & 15) * 8;
    const int ty8  = (t >> 4) * 8;
    const int i0   = bi * 128;
    const int j0   = bj * 128;
    const int lrow = t >> 1;          // 0..127
    const int lk   = (t & 1) * 4;     // float4 at lk and lk+8

    unsigned long long acc[8][4];
    float dl[8][8];
    float4 ra0, ra1, rb0, rb1;

    // ================= latent Gram (K = 128) =================
#pragma unroll
    for (int i = 0; i < 8; i++)
#pragma unroll
        for (int p = 0; p < 4; p++) acc[i][p] = 0ull;
    {
        const float* Ap = Lt + (size_t)(i0 + lrow) * LAT;
        const float* Bp = Lt + (size_t)(j0 + lrow) * LAT;
        LOADCHUNK(Ap, ra0, ra1, 0); LOADCHUNK(Bp, rb0, rb1, 0);
        STORECHUNK(As[0], ra0, ra1); STORECHUNK(Bs[0], rb0, rb1);
        __syncthreads();
        const int NC = LAT / 16;
#pragma unroll 1
        for (int c = 0; c < NC; c++) {
            int buf = c & 1;
            if (c + 1 < NC) { LOADCHUNK(Ap, ra0, ra1, (c + 1) * 16);
                              LOADCHUNK(Bp, rb0, rb1, (c + 1) * 16); }
            COMPUTE_CHUNK(As[buf], Bs[buf]);
            if (c + 1 < NC) { STORECHUNK(As[buf ^ 1], ra0, ra1);
                              STORECHUNK(Bs[buf ^ 1], rb0, rb1); }
            __syncthreads();
        }
    }
    // latent distances
#pragma unroll
    for (int ii = 0; ii < 8; ii++) {
        int i = i0 + ty8 + ii;
        float rli = __ldg(&rl[i]);
#pragma unroll
        for (int p = 0; p < 4; p++) {
            float g0, g1; UNPACK2(g0, g1, acc[ii][p]);
            int j = j0 + tx8 + 2 * p;
            float s0 = rli + __ldg(&rl[j])     - 2.f * g0;
            float s1 = rli + __ldg(&rl[j + 1]) - 2.f * g1;
            dl[ii][2 * p]     = sqrtf(fmaxf(s0, 0.f));
            dl[ii][2 * p + 1] = sqrtf(fmaxf(s1, 0.f));
        }
    }

    // ================= x Gram (K = 1024) =================
#pragma unroll
    for (int i = 0; i < 8; i++)
#pragma unroll
        for (int p = 0; p < 4; p++) acc[i][p] = 0ull;
    {
        const float* Ap = X + (size_t)(i0 + lrow) * DIM;
        const float* Bp = X + (size_t)(j0 + lrow) * DIM;
        LOADCHUNK(Ap, ra0, ra1, 0); LOADCHUNK(Bp, rb0, rb1, 0);
        __syncthreads();  // ensure latent-phase reads done before overwrite
        STORECHUNK(As[0], ra0, ra1); STORECHUNK(Bs[0], rb0, rb1);
        __syncthreads();
        const int NC = DIM / 16;
#pragma unroll 1
        for (int c = 0; c < NC; c++) {
            int buf = c & 1;
            if (c + 1 < NC) { LOADCHUNK(Ap, ra0, ra1, (c + 1) * 16);
                              LOADCHUNK(Bp, rb0, rb1, (c + 1) * 16); }
            COMPUTE_CHUNK(As[buf], Bs[buf]);
            if (c + 1 < NC) { STORECHUNK(As[buf ^ 1], ra0, ra1);
                              STORECHUNK(Bs[buf ^ 1], rb0, rb1); }
            __syncthreads();
        }
    }

    // x distances + stats (fp32 thread partials; fp64 only for reduction)
    float fs1 = 0.f, fs2 = 0.f, fs11 = 0.f, fs22 = 0.f, fs12 = 0.f;
#pragma unroll
    for (int ii = 0; ii < 8; ii++) {
        int i = i0 + ty8 + ii;
        float rxi = __ldg(&rx[i]);
#pragma unroll
        for (int p = 0; p < 4; p++) {
            float g0, g1; UNPACK2(g0, g1, acc[ii][p]);
#pragma unroll
            for (int q = 0; q < 2; q++) {
                int jj = 2 * p + q;
                int j = j0 + tx8 + jj;
                float g = (q == 0) ? g0 : g1;
                if (!diag || j > i) {
                    float sq = rxi + __ldg(&rx[j]) - 2.f * g;
                    float dx = sqrtf(fmaxf(sq, 0.f));
                    float dv = dl[ii][jj];
                    fs1  += dx;
                    fs2  += dv;
                    fs11 += dx * dx;
                    fs22 += dv * dv;
                    fs12 += dx * dv;
                }
            }
        }
    }

    float vals[5] = {fs1, fs2, fs11, fs22, fs12};
#pragma unroll
    for (int v = 0; v < 5; v++) {
        red[t] = (double)vals[v];
        __syncthreads();
        for (int off = 128; off > 0; off >>= 1) {
            if (t < off) red[t] += red[t + off];
            __syncthreads();
        }
        if (t == 0) atomicAdd(&g_stats[v], red[0]);
        __syncthreads();
    }
}

__global__ void finalize_kernel(float* __restrict__ out, long long idx) {
    const double n = (double)N_ROWS * (double)N_ROWS;
    double s1  = 2.0 * g_stats[0];
    double s2  = 2.0 * g_stats[1];
    double s11 = 2.0 * g_stats[2];
    double s22 = 2.0 * g_stats[3];
    double s12 = 2.0 * g_stats[4];
    double m1 = s1 / n;
    double m2 = s2 / n;
    double v1 = (s11 - n * m1 * m1) / (n - 1.0);
    double v2 = (s22 - n * m2 * m2) / (n - 1.0);
    double cov = s12 / n - m1 * m2;
    out[idx] = (float)(cov / sqrt(v1 * v2));
}

extern "C" void kernel_launch(void* const* d_in, const int* in_sizes, int n_in,
                              void* d_out, int out_size) {
    const float* x   = (const float*)d_in[0];
    const float* We1 = (const float*)d_in[1];
    const float* be1 = (const float*)d_in[2];
    const float* We2 = (const float*)d_in[3];
    const float* be2 = (const float*)d_in[4];
    const float* We3 = (const float*)d_in[5];
    const float* be3 = (const float*)d_in[6];
    const float* Wd1 = (const float*)d_in[7];
    const float* bd1 = (const float*)d_in[8];
    const float* Wd2 = (const float*)d_in[9];
    const float* bd2 = (const float*)d_in[10];
    const float* Wd3 = (const float*)d_in[11];
    const float* bd3 = (const float*)d_in[12];
    float* out = (float*)d_out;

    float* h1  = nullptr; cudaGetSymbolAddress((void**)&h1,  g_h1);
    float* h2  = nullptr; cudaGetSymbolAddress((void**)&h2,  g_h2);
    float* lat = nullptr; cudaGetSymbolAddress((void**)&lat, g_lat);
    float* dd1 = nullptr; cudaGetSymbolAddress((void**)&dd1, g_d1);
    float* dd2 = nullptr; cudaGetSymbolAddress((void**)&dd2, g_d2);
    float* rx  = nullptr; cudaGetSymbolAddress((void**)&rx,  g_rx);
    float* rl  = nullptr; cudaGetSymbolAddress((void**)&rl,  g_rl);

    zero_stats_kernel<<<1, 32>>>();

    // MLP chain (bias + LeakyReLU fused)
    gemm_bias_lrelu_kernel<<<dim3(H1 / 64,  N_ROWS / 64), 256>>>(x,   We1, be1, h1,  N_ROWS, H1,  DIM);
    gemm_bias_lrelu_kernel<<<dim3(H2 / 64,  N_ROWS / 64), 256>>>(h1,  We2, be2, h2,  N_ROWS, H2,  H1);
    gemm_bias_lrelu_kernel<<<dim3(LAT / 64, N_ROWS / 64), 256>>>(h2,  We3, be3, lat, N_ROWS, LAT, H2);
    gemm_bias_lrelu_kernel<<<dim3(H2 / 64,  N_ROWS / 64), 256>>>(lat, Wd1, bd1, dd1, N_ROWS, H2,  LAT);
    gemm_bias_lrelu_kernel<<<dim3(H1 / 64,  N_ROWS / 64), 256>>>(dd1, Wd2, bd2, dd2, N_ROWS, H1,  H2);
    gemm_bias_lrelu_kernel<<<dim3(DIM / 64, N_ROWS / 64), 256>>>(dd2, Wd3, bd3, out, N_ROWS, DIM, H1);

    // row squared norms
    rownorm_kernel<<<N_ROWS, 256>>>(x, rx, DIM);
    rownorm_kernel<<<N_ROWS, 128>>>(lat, rl, LAT);

    // fused pairwise-distance + correlation stats (upper triangle, 128x128 tiles)
    dist_stats_kernel<<<NB * (NB + 1) / 2, 256>>>(x, lat, rx, rl);

    // corr -> last output element
    finalize_kernel<<<1, 1>>>(out, (long long)out_size - 1);
}

// round 5
// speedup vs baseline: 1.9666x; 1.6720x over previous
#include <cuda_runtime.h>
#include <cuda_bf16.h>
#include <math.h>
#include <stdint.h>

#define N_ROWS 4096
#define DIM    1024
#define H1     512
#define H2     256
#define LAT    128
#define SLOPE  0.01f
#define NB     (N_ROWS / 128)        /* 32 tile-rows */
#define NKC_X  (DIM / 64)            /* 16 K-chunks for x  */
#define NKC_L  (LAT / 64)            /* 2  K-chunks for latent */
#define TILE_ELEMS 8192              /* 128 rows x 64 bf16 */
#define NT_CHUNKS  (NKC_L + NKC_X)   /* 18 */

#if defined(__CUDA_ARCH_FEAT_SM103_ALL) || defined(__CUDA_ARCH_FEAT_SM100_ALL) || defined(__CUDA_ARCH_FEAT_SM101_ALL)
#define HAS_TCGEN05 1
#else
#define HAS_TCGEN05 0
#endif

// -------- scratch (no allocations allowed) --------
__device__ float g_h1[N_ROWS * H1];
__device__ float g_h2[N_ROWS * H2];
__device__ float g_lat[N_ROWS * LAT];
__device__ float g_d1[N_ROWS * H2];
__device__ float g_d2[N_ROWS * H1];
__device__ float g_rx[N_ROWS];
__device__ float g_rl[N_ROWS];
__device__ double g_stats[5];
// pre-swizzled SW128 tile-major bf16 hi/lo copies
__device__ __align__(16) __nv_bfloat16 g_xh[NB * NKC_X * TILE_ELEMS];
__device__ __align__(16) __nv_bfloat16 g_xl[NB * NKC_X * TILE_ELEMS];
__device__ __align__(16) __nv_bfloat16 g_lh[NB * NKC_L * TILE_ELEMS];
__device__ __align__(16) __nv_bfloat16 g_ll[NB * NKC_L * TILE_ELEMS];

__global__ void zero_stats_kernel() {
    if (threadIdx.x < 5) g_stats[threadIdx.x] = 0.0;
}

// ================= PTX helpers =================
__device__ __forceinline__ uint32_t smem_u32(const void* p) {
    uint32_t a;
    asm("{ .reg .u64 t; cvta.to.shared.u64 t, %1; cvt.u32.u64 %0, t; }" : "=r"(a) : "l"(p));
    return a;
}
__device__ __forceinline__ uint32_t elect_one() {
    uint32_t p;
    asm volatile("{\n\t.reg .pred p;\n\telect.sync _|p, 0xFFFFFFFF;\n\tselp.b32 %0, 1, 0, p;\n\t}" : "=r"(p));
    return p;
}
#define MBAR_INIT(mbar, c) \
    asm volatile("mbarrier.init.shared.b64 [%0], %1;" :: "r"(mbar), "r"((uint32_t)(c)) : "memory")
#define MBAR_INVAL(mbar) \
    asm volatile("mbarrier.inval.shared.b64 [%0];" :: "r"(mbar) : "memory")

__device__ __forceinline__ void mbar_wait_parity(uint32_t mbar, uint32_t parity) {
    uint32_t done;
    asm volatile("{\n\t.reg .pred p;\n\t"
                 "mbarrier.try_wait.parity.acquire.cta.shared::cta.b64 p, [%1], %2;\n\t"
                 "selp.b32 %0, 1, 0, p;\n\t}" : "=r"(done) : "r"(mbar), "r"(parity) : "memory");
    if (!done) {
        asm volatile("{\n\t.reg .pred P1;\n\t"
                     "WL_%=:\n\t"
                     "mbarrier.try_wait.parity.acquire.cta.shared::cta.b64 P1, [%0], %1, 0x989680;\n\t"
                     "@P1 bra.uni WD_%=;\n\t"
                     "bra.uni WL_%=;\n\t"
                     "WD_%=:\n\t}" :: "r"(mbar), "r"(parity) : "memory");
    }
}

#if HAS_TCGEN05
#define TC_ALLOC(smem_addr, n) \
    asm volatile("tcgen05.alloc.cta_group::1.sync.aligned.shared::cta.b32 [%0], %1;" \
                 :: "r"(smem_addr), "r"((uint32_t)(n)) : "memory")
#define TC_DEALLOC(tmem, n) \
    asm volatile("tcgen05.dealloc.cta_group::1.sync.aligned.b32 %0, %1;" :: "r"(tmem), "r"((uint32_t)(n)))
#define TC_COMMIT(mbar) \
    asm volatile("tcgen05.commit.cta_group::1.mbarrier::arrive::one.shared::cluster.b64 [%0];" \
                 :: "r"(mbar) : "memory")
#define TC_FENCE_AFTER()  asm volatile("tcgen05.fence::after_thread_sync;" ::: "memory")
#define TC_WAIT_LD()      asm volatile("tcgen05.wait::ld.sync.aligned;" ::: "memory")
#define FENCE_ASYNC()     asm volatile("fence.proxy.async.shared::cta;" ::: "memory")

__device__ __forceinline__ void mma_f16_ss(uint32_t d_tmem, uint64_t a_desc, uint64_t b_desc,
                                           uint32_t idesc, bool accum) {
    uint32_t en = accum ? 1u : 0u;
    asm volatile("{\n\t.reg .pred p;\n\t"
                 "setp.ne.u32 p, %5, 0;\n\t"
                 "tcgen05.mma.cta_group::1.kind::f16 [%0], %1, %2, %3, {%4, %4, %4, %4}, p;\n\t}"
                 :: "r"(d_tmem), "l"(a_desc), "l"(b_desc), "r"(idesc), "r"(0u), "r"(en)
                 : "memory");
}

#define LDTM32(r, addr) \
    asm volatile("tcgen05.ld.sync.aligned.32x32b.x32.b32 " \
        "{%0, %1, %2, %3, %4, %5, %6, %7, %8, %9, %10, %11, %12, %13, %14, %15, " \
        " %16, %17, %18, %19, %20, %21, %22, %23, %24, %25, %26, %27, %28, %29, %30, %31}, [%32];" \
        : "=r"((r)[0]), "=r"((r)[1]), "=r"((r)[2]), "=r"((r)[3]), \
          "=r"((r)[4]), "=r"((r)[5]), "=r"((r)[6]), "=r"((r)[7]), \
          "=r"((r)[8]), "=r"((r)[9]), "=r"((r)[10]), "=r"((r)[11]), \
          "=r"((r)[12]), "=r"((r)[13]), "=r"((r)[14]), "=r"((r)[15]), \
          "=r"((r)[16]), "=r"((r)[17]), "=r"((r)[18]), "=r"((r)[19]), \
          "=r"((r)[20]), "=r"((r)[21]), "=r"((r)[22]), "=r"((r)[23]), \
          "=r"((r)[24]), "=r"((r)[25]), "=r"((r)[26]), "=r"((r)[27]), \
          "=r"((r)[28]), "=r"((r)[29]), "=r"((r)[30]), "=r"((r)[31]) \
        : "r"(addr))

// SW128 SMEM descriptor: layout=2 (SW128), version=1, SBO=64, LBO=1
static __device__ __forceinline__ uint64_t make_desc(uint32_t addr) {
    const uint64_t base = (uint64_t(2) << 61) | (uint64_t(1) << 46)
                        | (uint64_t(64) << 32) | (uint64_t(1) << 16);
    return base | ((uint64_t)(addr >> 4) & 0x3FFF);
}
// idesc: fp32 accum, bf16 a/b, N=128, M=128
#define IDESC_128x128 0x8200490u
#endif // HAS_TCGEN05

// ================= MLP GEMM (unchanged) =================
__global__ void gemm_bias_lrelu_kernel(const float* __restrict__ A,
                                       const float* __restrict__ W,
                                       const float* __restrict__ bias,
                                       float* __restrict__ C,
                                       int M, int N, int K) {
    __shared__ float As[16][65];
    __shared__ float Ws[16][65];

    const int t  = threadIdx.x;
    const int tx = t & 15;
    const int ty = t >> 4;
    const int m0 = blockIdx.y * 64;
    const int n0 = blockIdx.x * 64;
    const int lrow = t >> 2;
    const int lcol = (t & 3) * 4;
    const float* Ap = A + (size_t)(m0 + lrow) * K + lcol;
    const float* Wp = W + (size_t)(n0 + lrow) * K + lcol;

    float acc[4][4];
#pragma unroll
    for (int i = 0; i < 4; i++)
#pragma unroll
        for (int j = 0; j < 4; j++) acc[i][j] = 0.f;

    for (int k0 = 0; k0 < K; k0 += 16) {
        float4 va = *(const float4*)(Ap + k0);
        float4 vw = *(const float4*)(Wp + k0);
        As[lcol + 0][lrow] = va.x; As[lcol + 1][lrow] = va.y;
        As[lcol + 2][lrow] = va.z; As[lcol + 3][lrow] = va.w;
        Ws[lcol + 0][lrow] = vw.x; Ws[lcol + 1][lrow] = vw.y;
        Ws[lcol + 2][lrow] = vw.z; Ws[lcol + 3][lrow] = vw.w;
        __syncthreads();
#pragma unroll
        for (int kk = 0; kk < 16; kk++) {
            float a0 = As[kk][ty * 4 + 0], a1 = As[kk][ty * 4 + 1];
            float a2 = As[kk][ty * 4 + 2], a3 = As[kk][ty * 4 + 3];
            float w0 = Ws[kk][tx * 4 + 0], w1 = Ws[kk][tx * 4 + 1];
            float w2 = Ws[kk][tx * 4 + 2], w3 = Ws[kk][tx * 4 + 3];
            acc[0][0] += a0 * w0; acc[0][1] += a0 * w1; acc[0][2] += a0 * w2; acc[0][3] += a0 * w3;
            acc[1][0] += a1 * w0; acc[1][1] += a1 * w1; acc[1][2] += a1 * w2; acc[1][3] += a1 * w3;
            acc[2][0] += a2 * w0; acc[2][1] += a2 * w1; acc[2][2] += a2 * w2; acc[2][3] += a2 * w3;
            acc[3][0] += a3 * w0; acc[3][1] += a3 * w1; acc[3][2] += a3 * w2; acc[3][3] += a3 * w3;
        }
        __syncthreads();
    }

#pragma unroll
    for (int i = 0; i < 4; i++) {
        int m = m0 + ty * 4 + i;
#pragma unroll
        for (int j = 0; j < 4; j++) {
            int n = n0 + tx * 4 + j;
            float v = acc[i][j] + bias[n];
            C[(size_t)m * N + n] = (v >= 0.f) ? v : SLOPE * v;
        }
    }
}

// ================= row squared-norms =================
__global__ void rownorm_kernel(const float* __restrict__ X, float* __restrict__ r, int K) {
    int row = blockIdx.x;
    const float* p = X + (size_t)row * K;
    float s = 0.f;
    for (int k = threadIdx.x; k < K; k += blockDim.x) {
        float v = p[k];
        s += v * v;
    }
#pragma unroll
    for (int off = 16; off > 0; off >>= 1)
        s += __shfl_down_sync(0xffffffffu, s, off);
    __shared__ float sm[32];
    int lane = threadIdx.x & 31, wid = threadIdx.x >> 5;
    if (lane == 0) sm[wid] = s;
    __syncthreads();
    if (wid == 0) {
        int nw = blockDim.x >> 5;
        float v = (lane < nw) ? sm[lane] : 0.f;
#pragma unroll
        for (int off = 16; off > 0; off >>= 1)
            v += __shfl_down_sync(0xffffffffu, v, off);
        if (lane == 0) r[row] = v;
    }
}

// ================= bf16 hi/lo split + SW128 tile pre-swizzle =================
struct alignas(16) bf16x8 { __nv_bfloat16 v[8]; };

__global__ void convert_split_kernel(const float* __restrict__ src,
                                     __nv_bfloat16* __restrict__ dh,
                                     __nv_bfloat16* __restrict__ dl,
                                     int K, int nkc) {
    int idx = blockIdx.x * blockDim.x + threadIdx.x;  // one per 8 elements
    int gpr = K >> 3;
    int r  = idx / gpr;
    int k0 = (idx - r * gpr) * 8;
    if (r >= N_ROWS) return;

    const float* p = src + (size_t)r * K + k0;
    float4 v0 = *(const float4*)p;
    float4 v1 = *(const float4*)(p + 4);
    float f[8] = {v0.x, v0.y, v0.z, v0.w, v1.x, v1.y, v1.z, v1.w};

    bf16x8 ph, pl;
#pragma unroll
    for (int m = 0; m < 8; m++) {
        __nv_bfloat16 h = __float2bfloat16(f[m]);
        ph.v[m] = h;
        pl.v[m] = __float2bfloat16(f[m] - __bfloat162float(h));
    }

    int rb = r >> 7, lr = r & 127;
    int kc = k0 >> 6, g = (k0 & 63) >> 3;
    int gsw = g ^ (lr & 7);
    size_t off = (((size_t)rb * nkc + kc) * 128 + lr) * 64 + gsw * 8;
    *(bf16x8*)&dh[off] = ph;
    *(bf16x8*)&dl[off] = pl;
}

// ================= fused Gram + distance + stats =================
__global__ void __launch_bounds__(256, 1)
dist_stats_tc_kernel(const __nv_bfloat16* __restrict__ xh,
                     const __nv_bfloat16* __restrict__ xl,
                     const __nv_bfloat16* __restrict__ lh,
                     const __nv_bfloat16* __restrict__ ll,
                     const float* __restrict__ X,
                     const float* __restrict__ Lt,
                     const float* __restrict__ rx,
                     const float* __restrict__ rl) {
    // upper-triangle block decode
    int b = blockIdx.x;
    int bi = 0, rem = b;
    while (rem >= NB - bi) { rem -= NB - bi; bi++; }
    int bj = bi + rem;
    const bool diag = (bi == bj);
    const int i0 = bi * 128, j0 = bj * 128;

    __shared__ double red[256];
    const int t = threadIdx.x;

    float fs1 = 0.f, fs2 = 0.f, fs11 = 0.f, fs22 = 0.f, fs12 = 0.f;

#if HAS_TCGEN05
    extern __shared__ char dsm_raw[];
    char* dsm = (char*)(((uintptr_t)dsm_raw + 1023) & ~(uintptr_t)1023);
    __shared__ __align__(8) unsigned long long s_mbar[2];  // one per smem buffer
    __shared__ uint32_t s_tmem;

    const int wid = t >> 5;
    const int lid = t & 31;
    const uint32_t mbar0 = smem_u32(&s_mbar[0]);
    const uint32_t mbar1 = mbar0 + 8;

    if (wid == 0) TC_ALLOC(smem_u32(&s_tmem), 256);
    if (t == 0) { MBAR_INIT(mbar0, 1); MBAR_INIT(mbar1, 1); }
    __syncthreads();
    const uint32_t tmem = s_tmem;
    const uint32_t D_X = tmem, D_L = tmem + 128;
    const uint32_t smem_base = smem_u32(dsm);

    // chunk c commits to mbar[c&1]; its completion is the (c>>1)-th use of
    // that barrier -> wait parity (c>>1)&1. One barrier per buffer: with at
    // most 2 chunks outstanding, the same barrier is never >1 phase ahead,
    // so no parity aliasing (the R4 deadlock).
#pragma unroll 1
    for (int n = 0; n < NT_CHUNKS; n++) {
        if (n >= 2) {
            int c = n - 2;
            mbar_wait_parity((c & 1) ? mbar1 : mbar0, (uint32_t)((c >> 1) & 1));
        }

        char* buf = dsm + (size_t)(n & 1) * 65536;
        const bool is_lat = (n < NKC_L);
        const int kc = is_lat ? n : (n - NKC_L);
        const int nkc = is_lat ? NKC_L : NKC_X;
        const __nv_bfloat16* sh = is_lat ? lh : xh;
        const __nv_bfloat16* sl = is_lat ? ll : xl;

        const uint4* srcs[4] = {
            (const uint4*)(sh + ((size_t)bi * nkc + kc) * TILE_ELEMS),
            (const uint4*)(sl + ((size_t)bi * nkc + kc) * TILE_ELEMS),
            (const uint4*)(sh + ((size_t)bj * nkc + kc) * TILE_ELEMS),
            (const uint4*)(sl + ((size_t)bj * nkc + kc) * TILE_ELEMS)
        };
#pragma unroll
        for (int T = 0; T < 4; T++) {
            uint4* dst = (uint4*)(buf + T * 16384);
            const uint4* s = srcs[T];
#pragma unroll
            for (int w = 0; w < 4; w++)
                dst[t + w * 256] = s[t + w * 256];
        }
        FENCE_ASYNC();
        __syncthreads();

        if (wid == 0 && elect_one()) {
            uint32_t bufb = smem_base + (uint32_t)(n & 1) * 65536;
            uint64_t dAh = make_desc(bufb);
            uint64_t dAl = make_desc(bufb + 16384);
            uint64_t dBh = make_desc(bufb + 32768);
            uint64_t dBl = make_desc(bufb + 49152);
            uint32_t D = is_lat ? D_L : D_X;
            bool first = (n == 0) || (n == NKC_L);
#pragma unroll
            for (int s = 0; s < 4; s++) {
                uint64_t off = s * 2;
                mma_f16_ss(D, dAh + off, dBh + off, IDESC_128x128, !(first && s == 0));
                mma_f16_ss(D, dAh + off, dBl + off, IDESC_128x128, true);
                mma_f16_ss(D, dAl + off, dBh + off, IDESC_128x128, true);
            }
            TC_COMMIT((n & 1) ? mbar1 : mbar0);
        }
    }

    // drain both in-flight chunks, strictly in order: chunk 16 then chunk 17
    mbar_wait_parity(mbar0, (uint32_t)((16 >> 1) & 1));   // parity 0
    mbar_wait_parity(mbar1, (uint32_t)((17 >> 1) & 1));   // parity 0
    TC_FENCE_AFTER();

    // ---- epilogue: distances + stats ----
    const int wg  = wid >> 2;          // col half
    const int sub = wid & 3;           // TMEM subpartition -> i rows
    const int i = i0 + sub * 32 + lid;
    const float rxi = __ldg(&rx[i]);
    const float rli = __ldg(&rl[i]);

#pragma unroll
    for (int bb = 0; bb < 2; bb++) {
        const int colbase = wg * 64 + bb * 32;
        uint32_t xg[32], lg[32];
        LDTM32(xg, D_X + colbase);
        LDTM32(lg, D_L + colbase);
        TC_WAIT_LD();
#pragma unroll
        for (int c = 0; c < 32; c++) {
            int j = j0 + colbase + c;
            if (!diag || j > i) {
                float gx = __uint_as_float(xg[c]);
                float gl = __uint_as_float(lg[c]);
                float sqx = rxi + __ldg(&rx[j]) - 2.f * gx;
                float sql = rli + __ldg(&rl[j]) - 2.f * gl;
                float dx = sqrtf(fmaxf(sqx, 0.f));
                float dv = sqrtf(fmaxf(sql, 0.f));
                fs1  += dx;
                fs2  += dv;
                fs11 += dx * dx;
                fs22 += dv * dv;
                fs12 += dx * dv;
            }
        }
    }

    __syncthreads();   // all TMEM reads done before dealloc
    if (t == 0) { MBAR_INVAL(mbar0); MBAR_INVAL(mbar1); }
    __syncthreads();
    if (wid == 0) TC_DEALLOC(tmem, 256);

#else  // ---------------- fp32 fallback (compute_103 PTX pass) ----------------
    __shared__ __align__(16) float As[2][16][128];
    __shared__ __align__(16) float Bs[2][16][128];

    const int tx8  = (t & 15) * 8;
    const int ty8  = (t >> 4) * 8;
    const int lrow = t >> 1;
    const int lk   = (t & 1) * 4;

    float acc[8][8], dlv[8][8];
    float4 ra0, ra1, rb0, rb1;

#define FB_LOAD(Pp, koff) do { \
        ra0 = *(const float4*)((Pp) + (koff) + lk); \
        ra1 = *(const float4*)((Pp) + (koff) + lk + 8); } while (0)
#define FB_LOADB(Pp, koff) do { \
        rb0 = *(const float4*)((Pp) + (koff) + lk); \
        rb1 = *(const float4*)((Pp) + (koff) + lk + 8); } while (0)
#define FB_STORE(S) do { \
        S[lk + 0][lrow] = ra0.x; S[lk + 1][lrow] = ra0.y; \
        S[lk + 2][lrow] = ra0.z; S[lk + 3][lrow] = ra0.w; \
        S[lk + 8][lrow] = ra1.x; S[lk + 9][lrow] = ra1.y; \
        S[lk +10][lrow] = ra1.z; S[lk +11][lrow] = ra1.w; } while (0)
#define FB_STOREB(S) do { \
        S[lk + 0][lrow] = rb0.x; S[lk + 1][lrow] = rb0.y; \
        S[lk + 2][lrow] = rb0.z; S[lk + 3][lrow] = rb0.w; \
        S[lk + 8][lrow] = rb1.x; S[lk + 9][lrow] = rb1.y; \
        S[lk +10][lrow] = rb1.z; S[lk +11][lrow] = rb1.w; } while (0)
#define FB_COMPUTE(SA, SB) do { \
        _Pragma("unroll") \
        for (int kk = 0; kk < 16; kk++) { \
            float av[8], bv[8]; \
            *(float4*)&av[0] = *(const float4*)&SA[kk][ty8]; \
            *(float4*)&av[4] = *(const float4*)&SA[kk][ty8 + 4]; \
            *(float4*)&bv[0] = *(const float4*)&SB[kk][tx8]; \
            *(float4*)&bv[4] = *(const float4*)&SB[kk][tx8 + 4]; \
            _Pragma("unroll") \
            for (int ii = 0; ii < 8; ii++) \
                _Pragma("unroll") \
                for (int jj = 0; jj < 8; jj++) acc[ii][jj] += av[ii] * bv[jj]; \
        } } while (0)

    // latent Gram (K = 128)
#pragma unroll
    for (int ii = 0; ii < 8; ii++)
#pragma unroll
        for (int jj = 0; jj < 8; jj++) acc[ii][jj] = 0.f;
    {
        const float* Ap = Lt + (size_t)(i0 + lrow) * LAT;
        const float* Bp = Lt + (size_t)(j0 + lrow) * LAT;
        FB_LOAD(Ap, 0); FB_LOADB(Bp, 0);
        FB_STORE(As[0]); FB_STOREB(Bs[0]);
        __syncthreads();
        const int NC = LAT / 16;
#pragma unroll 1
        for (int c = 0; c < NC; c++) {
            int bf = c & 1;
            if (c + 1 < NC) { FB_LOAD(Ap, (c + 1) * 16); FB_LOADB(Bp, (c + 1) * 16); }
            FB_COMPUTE(As[bf], Bs[bf]);
            if (c + 1 < NC) { FB_STORE(As[bf ^ 1]); FB_STOREB(Bs[bf ^ 1]); }
            __syncthreads();
        }
    }
#pragma unroll
    for (int ii = 0; ii < 8; ii++) {
        int i = i0 + ty8 + ii;
        float rli = __ldg(&rl[i]);
#pragma unroll
        for (int jj = 0; jj < 8; jj++) {
            int j = j0 + tx8 + jj;
            float s = rli + __ldg(&rl[j]) - 2.f * acc[ii][jj];
            dlv[ii][jj] = sqrtf(fmaxf(s, 0.f));
        }
    }

    // x Gram (K = 1024)
#pragma unroll
    for (int ii = 0; ii < 8; ii++)
#pragma unroll
        for (int jj = 0; jj < 8; jj++) acc[ii][jj] = 0.f;
    {
        const float* Ap = X + (size_t)(i0 + lrow) * DIM;
        const float* Bp = X + (size_t)(j0 + lrow) * DIM;
        FB_LOAD(Ap, 0); FB_LOADB(Bp, 0);
        __syncthreads();
        FB_STORE(As[0]); FB_STOREB(Bs[0]);
        __syncthreads();
        const int NC = DIM / 16;
#pragma unroll 1
        for (int c = 0; c < NC; c++) {
            int bf = c & 1;
            if (c + 1 < NC) { FB_LOAD(Ap, (c + 1) * 16); FB_LOADB(Bp, (c + 1) * 16); }
            FB_COMPUTE(As[bf], Bs[bf]);
            if (c + 1 < NC) { FB_STORE(As[bf ^ 1]); FB_STOREB(Bs[bf ^ 1]); }
            __syncthreads();
        }
    }

#pragma unroll
    for (int ii = 0; ii < 8; ii++) {
        int i = i0 + ty8 + ii;
        float rxi = __ldg(&rx[i]);
#pragma unroll
        for (int jj = 0; jj < 8; jj++) {
            int j = j0 + tx8 + jj;
            if (!diag || j > i) {
                float sq = rxi + __ldg(&rx[j]) - 2.f * acc[ii][jj];
                float dx = sqrtf(fmaxf(sq, 0.f));
                float dv = dlv[ii][jj];
                fs1  += dx;
                fs2  += dv;
                fs11 += dx * dx;
                fs22 += dv * dv;
                fs12 += dx * dv;
            }
        }
    }
#endif // HAS_TCGEN05

    // ---- shared fp64 block reduction + atomics ----
    float vals[5] = {fs1, fs2, fs11, fs22, fs12};
#pragma unroll
    for (int v = 0; v < 5; v++) {
        red[t] = (double)vals[v];
        __syncthreads();
        for (int off = 128; off > 0; off >>= 1) {
            if (t < off) red[t] += red[t + off];
            __syncthreads();
        }
        if (t == 0) atomicAdd(&g_stats[v], red[0]);
        __syncthreads();
    }
}

__global__ void finalize_kernel(float* __restrict__ out, long long idx) {
    const double n = (double)N_ROWS * (double)N_ROWS;
    double s1  = 2.0 * g_stats[0];
    double s2  = 2.0 * g_stats[1];
    double s11 = 2.0 * g_stats[2];
    double s22 = 2.0 * g_stats[3];
    double s12 = 2.0 * g_stats[4];
    double m1 = s1 / n;
    double m2 = s2 / n;
    double v1 = (s11 - n * m1 * m1) / (n - 1.0);
    double v2 = (s22 - n * m2 * m2) / (n - 1.0);
    double cov = s12 / n - m1 * m2;
    out[idx] = (float)(cov / sqrt(v1 * v2));
}

extern "C" void kernel_launch(void* const* d_in, const int* in_sizes, int n_in,
                              void* d_out, int out_size) {
    const float* x   = (const float*)d_in[0];
    const float* We1 = (const float*)d_in[1];
    const float* be1 = (const float*)d_in[2];
    const float* We2 = (const float*)d_in[3];
    const float* be2 = (const float*)d_in[4];
    const float* We3 = (const float*)d_in[5];
    const float* be3 = (const float*)d_in[6];
    const float* Wd1 = (const float*)d_in[7];
    const float* bd1 = (const float*)d_in[8];
    const float* Wd2 = (const float*)d_in[9];
    const float* bd2 = (const float*)d_in[10];
    const float* Wd3 = (const float*)d_in[11];
    const float* bd3 = (const float*)d_in[12];
    float* out = (float*)d_out;

    float* h1  = nullptr; cudaGetSymbolAddress((void**)&h1,  g_h1);
    float* h2  = nullptr; cudaGetSymbolAddress((void**)&h2,  g_h2);
    float* lat = nullptr; cudaGetSymbolAddress((void**)&lat, g_lat);
    float* dd1 = nullptr; cudaGetSymbolAddress((void**)&dd1, g_d1);
    float* dd2 = nullptr; cudaGetSymbolAddress((void**)&dd2, g_d2);
    float* rx  = nullptr; cudaGetSymbolAddress((void**)&rx,  g_rx);
    float* rl  = nullptr; cudaGetSymbolAddress((void**)&rl,  g_rl);
    __nv_bfloat16* xh = nullptr; cudaGetSymbolAddress((void**)&xh, g_xh);
    __nv_bfloat16* xl = nullptr; cudaGetSymbolAddress((void**)&xl, g_xl);
    __nv_bfloat16* lh = nullptr; cudaGetSymbolAddress((void**)&lh, g_lh);
    __nv_bfloat16* ll = nullptr; cudaGetSymbolAddress((void**)&ll, g_ll);

    zero_stats_kernel<<<1, 32>>>();

    // x split can start immediately
    convert_split_kernel<<<(N_ROWS * DIM / 8) / 256, 256>>>(x, xh, xl, DIM, NKC_X);

    // MLP chain
    gemm_bias_lrelu_kernel<<<dim3(H1 / 64,  N_ROWS / 64), 256>>>(x,   We1, be1, h1,  N_ROWS, H1,  DIM);
    gemm_bias_lrelu_kernel<<<dim3(H2 / 64,  N_ROWS / 64), 256>>>(h1,  We2, be2, h2,  N_ROWS, H2,  H1);
    gemm_bias_lrelu_kernel<<<dim3(LAT / 64, N_ROWS / 64), 256>>>(h2,  We3, be3, lat, N_ROWS, LAT, H2);

    // latent split (after encoder)
    convert_split_kernel<<<(N_ROWS * LAT / 8) / 256, 256>>>(lat, lh, ll, LAT, NKC_L);
    rownorm_kernel<<<N_ROWS, 256>>>(x, rx, DIM);
    rownorm_kernel<<<N_ROWS, 128>>>(lat, rl, LAT);

    // decoder
    gemm_bias_lrelu_kernel<<<dim3(H2 / 64,  N_ROWS / 64), 256>>>(lat, Wd1, bd1, dd1, N_ROWS, H2,  LAT);
    gemm_bias_lrelu_kernel<<<dim3(H1 / 64,  N_ROWS / 64), 256>>>(dd1, Wd2, bd2, dd2, N_ROWS, H1,  H2);
    gemm_bias_lrelu_kernel<<<dim3(DIM / 64, N_ROWS / 64), 256>>>(dd2, Wd3, bd3, out, N_ROWS, DIM, H1);

    // fused Gram + distance + correlation stats
    const int dyn_smem = 2 * 65536 + 1024;
    cudaFuncSetAttribute(dist_stats_tc_kernel, cudaFuncAttributeMaxDynamicSharedMemorySize, dyn_smem);
    dist_stats_tc_kernel<<<NB * (NB + 1) / 2, 256, dyn_smem>>>(xh, xl, lh, ll, x, lat, rx, rl);

    finalize_kernel<<<1, 1>>>(out, (long long)out_size - 1);
}

// round 6
// speedup vs baseline: 4.4167x; 2.2459x over previous
#include <cuda_runtime.h>
#include <cuda_bf16.h>
#include <math.h>
#include <stdint.h>

#define N_ROWS 4096
#define DIM    1024
#define H1     512
#define H2     256
#define LAT    128
#define SLOPE  0.01f
#define NB     (N_ROWS / 128)
#define NKC_X  (DIM / 64)
#define NKC_L  (LAT / 64)
#define TILE_ELEMS 8192              /* 128 rows x 64 bf16 */
#define NT_CHUNKS  (NKC_L + NKC_X)

#if defined(__CUDA_ARCH_FEAT_SM103_ALL) || defined(__CUDA_ARCH_FEAT_SM100_ALL) || defined(__CUDA_ARCH_FEAT_SM101_ALL)
#define HAS_TCGEN05 1
#else
#define HAS_TCGEN05 0
#endif

// -------- scratch --------
__device__ float g_lat[N_ROWS * LAT];
__device__ float g_rx[N_ROWS];
__device__ float g_rl[N_ROWS];
__device__ double g_stats[5];
// pre-swizzled tile-major bf16 hi/lo: inputs + activations
__device__ __align__(16) __nv_bfloat16 g_xh[NB * NKC_X * TILE_ELEMS];
__device__ __align__(16) __nv_bfloat16 g_xl[NB * NKC_X * TILE_ELEMS];
__device__ __align__(16) __nv_bfloat16 g_lh[NB * NKC_L * TILE_ELEMS];
__device__ __align__(16) __nv_bfloat16 g_ll[NB * NKC_L * TILE_ELEMS];
__device__ __align__(16) __nv_bfloat16 g_a1h[N_ROWS * H1], g_a1l[N_ROWS * H1];
__device__ __align__(16) __nv_bfloat16 g_a2h[N_ROWS * H2], g_a2l[N_ROWS * H2];
__device__ __align__(16) __nv_bfloat16 g_a4h[N_ROWS * H2], g_a4l[N_ROWS * H2];
__device__ __align__(16) __nv_bfloat16 g_a5h[N_ROWS * H1], g_a5l[N_ROWS * H1];
// weight splits
__device__ __align__(16) __nv_bfloat16 g_we1h[H1 * DIM], g_we1l[H1 * DIM];
__device__ __align__(16) __nv_bfloat16 g_we2h[H2 * H1],  g_we2l[H2 * H1];
__device__ __align__(16) __nv_bfloat16 g_we3h[LAT * H2], g_we3l[LAT * H2];
__device__ __align__(16) __nv_bfloat16 g_wd1h[H2 * LAT], g_wd1l[H2 * LAT];
__device__ __align__(16) __nv_bfloat16 g_wd2h[H1 * H2],  g_wd2l[H1 * H2];
__device__ __align__(16) __nv_bfloat16 g_wd3h[DIM * H1], g_wd3l[DIM * H1];

__global__ void zero_stats_kernel() {
    if (threadIdx.x < 5) g_stats[threadIdx.x] = 0.0;
}

// ================= PTX helpers =================
__device__ __forceinline__ uint32_t smem_u32(const void* p) {
    uint32_t a;
    asm("{ .reg .u64 t; cvta.to.shared.u64 t, %1; cvt.u32.u64 %0, t; }" : "=r"(a) : "l"(p));
    return a;
}
__device__ __forceinline__ uint32_t elect_one() {
    uint32_t p;
    asm volatile("{\n\t.reg .pred p;\n\telect.sync _|p, 0xFFFFFFFF;\n\tselp.b32 %0, 1, 0, p;\n\t}" : "=r"(p));
    return p;
}
#define MBAR_INIT(mbar, c) \
    asm volatile("mbarrier.init.shared.b64 [%0], %1;" :: "r"(mbar), "r"((uint32_t)(c)) : "memory")
#define MBAR_INVAL(mbar) \
    asm volatile("mbarrier.inval.shared.b64 [%0];" :: "r"(mbar) : "memory")

__device__ __forceinline__ void mbar_wait_parity(uint32_t mbar, uint32_t parity) {
    uint32_t done;
    asm volatile("{\n\t.reg .pred p;\n\t"
                 "mbarrier.try_wait.parity.acquire.cta.shared::cta.b64 p, [%1], %2;\n\t"
                 "selp.b32 %0, 1, 0, p;\n\t}" : "=r"(done) : "r"(mbar), "r"(parity) : "memory");
    if (!done) {
        asm volatile("{\n\t.reg .pred P1;\n\t"
                     "WL_%=:\n\t"
                     "mbarrier.try_wait.parity.acquire.cta.shared::cta.b64 P1, [%0], %1, 0x989680;\n\t"
                     "@P1 bra.uni WD_%=;\n\t"
                     "bra.uni WL_%=;\n\t"
                     "WD_%=:\n\t}" :: "r"(mbar), "r"(parity) : "memory");
    }
}

#if HAS_TCGEN05
#define TC_ALLOC(smem_addr, n) \
    asm volatile("tcgen05.alloc.cta_group::1.sync.aligned.shared::cta.b32 [%0], %1;" \
                 :: "r"(smem_addr), "r"((uint32_t)(n)) : "memory")
#define TC_DEALLOC(tmem, n) \
    asm volatile("tcgen05.dealloc.cta_group::1.sync.aligned.b32 %0, %1;" :: "r"(tmem), "r"((uint32_t)(n)))
#define TC_COMMIT(mbar) \
    asm volatile("tcgen05.commit.cta_group::1.mbarrier::arrive::one.shared::cluster.b64 [%0];" \
                 :: "r"(mbar) : "memory")
#define TC_FENCE_AFTER()  asm volatile("tcgen05.fence::after_thread_sync;" ::: "memory")
#define TC_WAIT_LD()      asm volatile("tcgen05.wait::ld.sync.aligned;" ::: "memory")
#define FENCE_ASYNC()     asm volatile("fence.proxy.async.shared::cta;" ::: "memory")

__device__ __forceinline__ void mma_f16_ss(uint32_t d_tmem, uint64_t a_desc, uint64_t b_desc,
                                           uint32_t idesc, bool accum) {
    uint32_t en = accum ? 1u : 0u;
    asm volatile("{\n\t.reg .pred p;\n\t"
                 "setp.ne.u32 p, %5, 0;\n\t"
                 "tcgen05.mma.cta_group::1.kind::f16 [%0], %1, %2, %3, {%4, %4, %4, %4}, p;\n\t}"
                 :: "r"(d_tmem), "l"(a_desc), "l"(b_desc), "r"(idesc), "r"(0u), "r"(en)
                 : "memory");
}

#define LDTM32(r, addr) \
    asm volatile("tcgen05.ld.sync.aligned.32x32b.x32.b32 " \
        "{%0, %1, %2, %3, %4, %5, %6, %7, %8, %9, %10, %11, %12, %13, %14, %15, " \
        " %16, %17, %18, %19, %20, %21, %22, %23, %24, %25, %26, %27, %28, %29, %30, %31}, [%32];" \
        : "=r"((r)[0]), "=r"((r)[1]), "=r"((r)[2]), "=r"((r)[3]), \
          "=r"((r)[4]), "=r"((r)[5]), "=r"((r)[6]), "=r"((r)[7]), \
          "=r"((r)[8]), "=r"((r)[9]), "=r"((r)[10]), "=r"((r)[11]), \
          "=r"((r)[12]), "=r"((r)[13]), "=r"((r)[14]), "=r"((r)[15]), \
          "=r"((r)[16]), "=r"((r)[17]), "=r"((r)[18]), "=r"((r)[19]), \
          "=r"((r)[20]), "=r"((r)[21]), "=r"((r)[22]), "=r"((r)[23]), \
          "=r"((r)[24]), "=r"((r)[25]), "=r"((r)[26]), "=r"((r)[27]), \
          "=r"((r)[28]), "=r"((r)[29]), "=r"((r)[30]), "=r"((r)[31]) \
        : "r"(addr))

static __device__ __forceinline__ uint64_t make_desc(uint32_t addr) {
    const uint64_t base = (uint64_t(2) << 61) | (uint64_t(1) << 46)
                        | (uint64_t(64) << 32) | (uint64_t(1) << 16);
    return base | ((uint64_t)(addr >> 4) & 0x3FFF);
}
#define IDESC_128x128 0x8200490u
#endif // HAS_TCGEN05

// ================= row squared-norms =================
__global__ void rownorm_kernel(const float* __restrict__ X, float* __restrict__ r, int K) {
    int row = blockIdx.x;
    const float* p = X + (size_t)row * K;
    float s = 0.f;
    for (int k = threadIdx.x; k < K; k += blockDim.x) {
        float v = p[k];
        s += v * v;
    }
#pragma unroll
    for (int off = 16; off > 0; off >>= 1)
        s += __shfl_down_sync(0xffffffffu, s, off);
    __shared__ float sm[32];
    int lane = threadIdx.x & 31, wid = threadIdx.x >> 5;
    if (lane == 0) sm[wid] = s;
    __syncthreads();
    if (wid == 0) {
        int nw = blockDim.x >> 5;
        float v = (lane < nw) ? sm[lane] : 0.f;
#pragma unroll
        for (int off = 16; off > 0; off >>= 1)
            v += __shfl_down_sync(0xffffffffu, v, off);
        if (lane == 0) r[row] = v;
    }
}

// ================= bf16 hi/lo split + tile pre-swizzle =================
struct alignas(16) bf16x8 { __nv_bfloat16 v[8]; };

__global__ void convert_split_kernel(const float* __restrict__ src,
                                     __nv_bfloat16* __restrict__ dh,
                                     __nv_bfloat16* __restrict__ dl,
                                     int rows, int K) {
    int idx = blockIdx.x * blockDim.x + threadIdx.x;
    int gpr = K >> 3;
    int r  = idx / gpr;
    int k0 = (idx - r * gpr) * 8;
    if (r >= rows) return;
    int nkc = K >> 6;

    const float* p = src + (size_t)r * K + k0;
    float4 v0 = *(const float4*)p;
    float4 v1 = *(const float4*)(p + 4);
    float f[8] = {v0.x, v0.y, v0.z, v0.w, v1.x, v1.y, v1.z, v1.w};

    bf16x8 ph, pl;
#pragma unroll
    for (int m = 0; m < 8; m++) {
        __nv_bfloat16 h = __float2bfloat16(f[m]);
        ph.v[m] = h;
        pl.v[m] = __float2bfloat16(f[m] - __bfloat162float(h));
    }

    int rb = r >> 7, lr = r & 127;
    int kc = k0 >> 6, g = (k0 & 63) >> 3;
    int gsw = g ^ (lr & 7);
    size_t off = (((size_t)rb * nkc + kc) * 128 + lr) * 64 + gsw * 8;
    *(bf16x8*)&dh[off] = ph;
    *(bf16x8*)&dl[off] = pl;
}

// ================= tcgen05 GEMM + bias + LeakyReLU =================
// C[m,n] = lrelu(sum_k A[m,k] W[n,k] + b[n]); A,W given as hi/lo swizzled tiles.
// Writes optional fp32 C and optional bf16 hi/lo swizzled activation output.
__global__ void __launch_bounds__(256, 1)
tc_gemm_bias_lrelu(const __nv_bfloat16* __restrict__ ah, const __nv_bfloat16* __restrict__ al,
                   const __nv_bfloat16* __restrict__ wh, const __nv_bfloat16* __restrict__ wl,
                   const float* __restrict__ bias,
                   float* __restrict__ Cfp,
                   __nv_bfloat16* __restrict__ oh, __nv_bfloat16* __restrict__ ol,
                   int N, int NC, int write_fp32, int write_split) {
    const int nb = blockIdx.x, mb = blockIdx.y;
    const int n0 = nb * 128, m0 = mb * 128;
    const int t = threadIdx.x;

#if HAS_TCGEN05
    extern __shared__ char dsm_raw[];
    char* dsm = (char*)(((uintptr_t)dsm_raw + 1023) & ~(uintptr_t)1023);
    __shared__ __align__(8) unsigned long long s_mbar[2];
    __shared__ uint32_t s_tmem;

    const int wid = t >> 5;
    const int lid = t & 31;
    const uint32_t mbar0 = smem_u32(&s_mbar[0]);
    const uint32_t mbar1 = mbar0 + 8;

    if (wid == 0) TC_ALLOC(smem_u32(&s_tmem), 128);
    if (t == 0) { MBAR_INIT(mbar0, 1); MBAR_INIT(mbar1, 1); }
    __syncthreads();
    const uint32_t D = s_tmem;
    const uint32_t smem_base = smem_u32(dsm);

#pragma unroll 1
    for (int n = 0; n < NC; n++) {
        if (n >= 2) {
            int c = n - 2;
            mbar_wait_parity((c & 1) ? mbar1 : mbar0, (uint32_t)((c >> 1) & 1));
        }
        char* buf = dsm + (size_t)(n & 1) * 65536;
        const uint4* srcs[4] = {
            (const uint4*)(ah + ((size_t)mb * NC + n) * TILE_ELEMS),
            (const uint4*)(al + ((size_t)mb * NC + n) * TILE_ELEMS),
            (const uint4*)(wh + ((size_t)nb * NC + n) * TILE_ELEMS),
            (const uint4*)(wl + ((size_t)nb * NC + n) * TILE_ELEMS)
        };
#pragma unroll
        for (int T = 0; T < 4; T++) {
            uint4* dst = (uint4*)(buf + T * 16384);
            const uint4* s = srcs[T];
#pragma unroll
            for (int w = 0; w < 4; w++)
                dst[t + w * 256] = s[t + w * 256];
        }
        FENCE_ASYNC();
        __syncthreads();

        if (wid == 0 && elect_one()) {
            uint32_t bufb = smem_base + (uint32_t)(n & 1) * 65536;
            uint64_t dAh = make_desc(bufb);
            uint64_t dAl = make_desc(bufb + 16384);
            uint64_t dWh = make_desc(bufb + 32768);
            uint64_t dWl = make_desc(bufb + 49152);
            bool first = (n == 0);
#pragma unroll
            for (int s = 0; s < 4; s++) {
                uint64_t off = s * 2;
                mma_f16_ss(D, dAh + off, dWh + off, IDESC_128x128, !(first && s == 0));
                mma_f16_ss(D, dAh + off, dWl + off, IDESC_128x128, true);
                mma_f16_ss(D, dAl + off, dWh + off, IDESC_128x128, true);
            }
            TC_COMMIT((n & 1) ? mbar1 : mbar0);
        }
    }
    {
        int c0 = (NC >= 2) ? NC - 2 : 0;
        for (int c = c0; c < NC; c++)
            mbar_wait_parity((c & 1) ? mbar1 : mbar0, (uint32_t)((c >> 1) & 1));
    }
    TC_FENCE_AFTER();

    // epilogue
    const int wg  = wid >> 2;
    const int sub = wid & 3;
    const int lr  = sub * 32 + lid;           // local row 0..127
    const int m   = m0 + lr;
    const int nkc_out = N >> 6;

#pragma unroll
    for (int bb = 0; bb < 2; bb++) {
        const int colbase = wg * 64 + bb * 32;
        uint32_t dr[32];
        LDTM32(dr, D + colbase);
        TC_WAIT_LD();
        float v[32];
#pragma unroll
        for (int c = 0; c < 32; c++) {
            float x = __uint_as_float(dr[c]) + __ldg(&bias[n0 + colbase + c]);
            v[c] = (x >= 0.f) ? x : SLOPE * x;
        }
        if (write_fp32) {
#pragma unroll
            for (int c = 0; c < 32; c++)
                Cfp[(size_t)m * N + n0 + colbase + c] = v[c];
        }
        if (write_split) {
#pragma unroll
            for (int g8 = 0; g8 < 4; g8++) {
                int nn = n0 + colbase + g8 * 8;
                int kc = nn >> 6, g = (nn & 63) >> 3;
                int gsw = g ^ (lr & 7);
                size_t off = (((size_t)mb * nkc_out + kc) * 128 + lr) * 64 + gsw * 8;
                bf16x8 ph, pl;
#pragma unroll
                for (int e = 0; e < 8; e++) {
                    float x = v[g8 * 8 + e];
                    __nv_bfloat16 h = __float2bfloat16(x);
                    ph.v[e] = h;
                    pl.v[e] = __float2bfloat16(x - __bfloat162float(h));
                }
                *(bf16x8*)&oh[off] = ph;
                *(bf16x8*)&ol[off] = pl;
            }
        }
    }

    __syncthreads();
    if (t == 0) { MBAR_INVAL(mbar0); MBAR_INVAL(mbar1); }
    __syncthreads();
    if (wid == 0) TC_DEALLOC(D, 128);

#else  // ------- correctness-only fallback (compute_103 PTX pass; never the selected cubin) -------
    const int K = NC * 64;
    const int lr0 = t & 127;
    const int m = m0 + lr0;
    const int jh = (t >> 7) * 64;
    const int nkc_out = N >> 6;
    for (int jj = 0; jj < 64; jj++) {
        int nn = n0 + jh + jj;
        int wr = nn, wrb = wr >> 7, wlr = wr & 127;
        float acc = 0.f;
        for (int k = 0; k < K; k++) {
            int kc = k >> 6, g = (k & 63) >> 3, e = k & 7;
            size_t aoff = (((size_t)mb * NC + kc) * 128 + lr0) * 64 + (size_t)((g ^ (lr0 & 7)) * 8 + e);
            size_t woff = (((size_t)wrb * NC + kc) * 128 + wlr) * 64 + (size_t)((g ^ (wlr & 7)) * 8 + e);
            float av = __bfloat162float(ah[aoff]) + __bfloat162float(al[aoff]);
            float wv = __bfloat162float(wh[woff]) + __bfloat162float(wl[woff]);
            acc += av * wv;
        }
        float x = acc + bias[nn];
        x = (x >= 0.f) ? x : SLOPE * x;
        if (write_fp32) Cfp[(size_t)m * N + nn] = x;
        if (write_split) {
            __nv_bfloat16 h = __float2bfloat16(x);
            int kc = nn >> 6, g = (nn & 63) >> 3;
            size_t off = (((size_t)mb * nkc_out + kc) * 128 + lr0) * 64 + (size_t)((g ^ (lr0 & 7)) * 8 + (nn & 7));
            oh[off] = h;
            ol[off] = __float2bfloat16(x - __bfloat162float(h));
        }
    }
#endif
}

// ================= fused Gram + distance + stats (unchanged from R5) =================
__global__ void __launch_bounds__(256, 1)
dist_stats_tc_kernel(const __nv_bfloat16* __restrict__ xh,
                     const __nv_bfloat16* __restrict__ xl,
                     const __nv_bfloat16* __restrict__ lh,
                     const __nv_bfloat16* __restrict__ ll,
                     const float* __restrict__ rx,
                     const float* __restrict__ rl) {
    int b = blockIdx.x;
    int bi = 0, rem = b;
    while (rem >= NB - bi) { rem -= NB - bi; bi++; }
    int bj = bi + rem;
    const bool diag = (bi == bj);
    const int i0 = bi * 128, j0 = bj * 128;

    __shared__ double red[256];
    const int t = threadIdx.x;

    float fs1 = 0.f, fs2 = 0.f, fs11 = 0.f, fs22 = 0.f, fs12 = 0.f;

#if HAS_TCGEN05
    extern __shared__ char dsm_raw[];
    char* dsm = (char*)(((uintptr_t)dsm_raw + 1023) & ~(uintptr_t)1023);
    __shared__ __align__(8) unsigned long long s_mbar[2];
    __shared__ uint32_t s_tmem;

    const int wid = t >> 5;
    const int lid = t & 31;
    const uint32_t mbar0 = smem_u32(&s_mbar[0]);
    const uint32_t mbar1 = mbar0 + 8;

    if (wid == 0) TC_ALLOC(smem_u32(&s_tmem), 256);
    if (t == 0) { MBAR_INIT(mbar0, 1); MBAR_INIT(mbar1, 1); }
    __syncthreads();
    const uint32_t tmem = s_tmem;
    const uint32_t D_X = tmem, D_L = tmem + 128;
    const uint32_t smem_base = smem_u32(dsm);

#pragma unroll 1
    for (int n = 0; n < NT_CHUNKS; n++) {
        if (n >= 2) {
            int c = n - 2;
            mbar_wait_parity((c & 1) ? mbar1 : mbar0, (uint32_t)((c >> 1) & 1));
        }
        char* buf = dsm + (size_t)(n & 1) * 65536;
        const bool is_lat = (n < NKC_L);
        const int kc = is_lat ? n : (n - NKC_L);
        const int nkc = is_lat ? NKC_L : NKC_X;
        const __nv_bfloat16* sh = is_lat ? lh : xh;
        const __nv_bfloat16* sl = is_lat ? ll : xl;

        const uint4* srcs[4] = {
            (const uint4*)(sh + ((size_t)bi * nkc + kc) * TILE_ELEMS),
            (const uint4*)(sl + ((size_t)bi * nkc + kc) * TILE_ELEMS),
            (const uint4*)(sh + ((size_t)bj * nkc + kc) * TILE_ELEMS),
            (const uint4*)(sl + ((size_t)bj * nkc + kc) * TILE_ELEMS)
        };
#pragma unroll
        for (int T = 0; T < 4; T++) {
            uint4* dst = (uint4*)(buf + T * 16384);
            const uint4* s = srcs[T];
#pragma unroll
            for (int w = 0; w < 4; w++)
                dst[t + w * 256] = s[t + w * 256];
        }
        FENCE_ASYNC();
        __syncthreads();

        if (wid == 0 && elect_one()) {
            uint32_t bufb = smem_base + (uint32_t)(n & 1) * 65536;
            uint64_t dAh = make_desc(bufb);
            uint64_t dAl = make_desc(bufb + 16384);
            uint64_t dBh = make_desc(bufb + 32768);
            uint64_t dBl = make_desc(bufb + 49152);
            uint32_t D = is_lat ? D_L : D_X;
            bool first = (n == 0) || (n == NKC_L);
#pragma unroll
            for (int s = 0; s < 4; s++) {
                uint64_t off = s * 2;
                mma_f16_ss(D, dAh + off, dBh + off, IDESC_128x128, !(first && s == 0));
                mma_f16_ss(D, dAh + off, dBl + off, IDESC_128x128, true);
                mma_f16_ss(D, dAl + off, dBh + off, IDESC_128x128, true);
            }
            TC_COMMIT((n & 1) ? mbar1 : mbar0);
        }
    }

    mbar_wait_parity(mbar0, 0);
    mbar_wait_parity(mbar1, 0);
    TC_FENCE_AFTER();

    const int wg  = wid >> 2;
    const int sub = wid & 3;
    const int i = i0 + sub * 32 + lid;
    const float rxi = __ldg(&rx[i]);
    const float rli = __ldg(&rl[i]);

#pragma unroll
    for (int bb = 0; bb < 2; bb++) {
        const int colbase = wg * 64 + bb * 32;
        uint32_t xg[32], lg[32];
        LDTM32(xg, D_X + colbase);
        LDTM32(lg, D_L + colbase);
        TC_WAIT_LD();
#pragma unroll
        for (int c = 0; c < 32; c++) {
            int j = j0 + colbase + c;
            if (!diag || j > i) {
                float gx = __uint_as_float(xg[c]);
                float gl = __uint_as_float(lg[c]);
                float sqx = rxi + __ldg(&rx[j]) - 2.f * gx;
                float sql = rli + __ldg(&rl[j]) - 2.f * gl;
                float dx = sqrtf(fmaxf(sqx, 0.f));
                float dv = sqrtf(fmaxf(sql, 0.f));
                fs1  += dx;
                fs2  += dv;
                fs11 += dx * dx;
                fs22 += dv * dv;
                fs12 += dx * dv;
            }
        }
    }

    __syncthreads();
    if (t == 0) { MBAR_INVAL(mbar0); MBAR_INVAL(mbar1); }
    __syncthreads();
    if (wid == 0) TC_DEALLOC(tmem, 256);

#else  // fallback: dequant-based fp32 (correct, slow, never selected on GB300)
    const int tx8  = (t & 15) * 8;
    const int ty8  = (t >> 4) * 8;
    for (int ii = 0; ii < 8; ii++) {
        int i = i0 + ty8 + ii;
        float rxi = rx[i], rli = rl[i];
        int ib = i >> 7, ilr = i & 127;
        for (int jj = 0; jj < 8; jj++) {
            int j = j0 + tx8 + jj;
            if (diag && j <= i) continue;
            int jb = j >> 7, jlr = j & 127;
            float gx = 0.f, gl = 0.f;
            for (int k = 0; k < DIM; k++) {
                int kc = k >> 6, g = (k & 63) >> 3, e = k & 7;
                size_t ioff = (((size_t)ib * NKC_X + kc) * 128 + ilr) * 64 + (size_t)((g ^ (ilr & 7)) * 8 + e);
                size_t joff = (((size_t)jb * NKC_X + kc) * 128 + jlr) * 64 + (size_t)((g ^ (jlr & 7)) * 8 + e);
                gx += (__bfloat162float(xh[ioff]) + __bfloat162float(xl[ioff]))
                    * (__bfloat162float(xh[joff]) + __bfloat162float(xl[joff]));
            }
            for (int k = 0; k < LAT; k++) {
                int kc = k >> 6, g = (k & 63) >> 3, e = k & 7;
                size_t ioff = (((size_t)ib * NKC_L + kc) * 128 + ilr) * 64 + (size_t)((g ^ (ilr & 7)) * 8 + e);
                size_t joff = (((size_t)jb * NKC_L + kc) * 128 + jlr) * 64 + (size_t)((g ^ (jlr & 7)) * 8 + e);
                gl += (__bfloat162float(lh[ioff]) + __bfloat162float(ll[ioff]))
                    * (__bfloat162float(lh[joff]) + __bfloat162float(ll[joff]));
            }
            float dx = sqrtf(fmaxf(rxi + rx[j] - 2.f * gx, 0.f));
            float dv = sqrtf(fmaxf(rli + rl[j] - 2.f * gl, 0.f));
            fs1 += dx; fs2 += dv; fs11 += dx * dx; fs22 += dv * dv; fs12 += dx * dv;
        }
    }
#endif

    float vals[5] = {fs1, fs2, fs11, fs22, fs12};
#pragma unroll
    for (int v = 0; v < 5; v++) {
        red[t] = (double)vals[v];
        __syncthreads();
        for (int off = 128; off > 0; off >>= 1) {
            if (t < off) red[t] += red[t + off];
            __syncthreads();
        }
        if (t == 0) atomicAdd(&g_stats[v], red[0]);
        __syncthreads();
    }
}

__global__ void finalize_kernel(float* __restrict__ out, long long idx) {
    const double n = (double)N_ROWS * (double)N_ROWS;
    double s1  = 2.0 * g_stats[0];
    double s2  = 2.0 * g_stats[1];
    double s11 = 2.0 * g_stats[2];
    double s22 = 2.0 * g_stats[3];
    double s12 = 2.0 * g_stats[4];
    double m1 = s1 / n;
    double m2 = s2 / n;
    double v1 = (s11 - n * m1 * m1) / (n - 1.0);
    double v2 = (s22 - n * m2 * m2) / (n - 1.0);
    double cov = s12 / n - m1 * m2;
    out[idx] = (float)(cov / sqrt(v1 * v2));
}

extern "C" void kernel_launch(void* const* d_in, const int* in_sizes, int n_in,
                              void* d_out, int out_size) {
    const float* x   = (const float*)d_in[0];
    const float* We1 = (const float*)d_in[1];
    const float* be1 = (const float*)d_in[2];
    const float* We2 = (const float*)d_in[3];
    const float* be2 = (const float*)d_in[4];
    const float* We3 = (const float*)d_in[5];
    const float* be3 = (const float*)d_in[6];
    const float* Wd1 = (const float*)d_in[7];
    const float* bd1 = (const float*)d_in[8];
    const float* Wd2 = (const float*)d_in[9];
    const float* bd2 = (const float*)d_in[10];
    const float* Wd3 = (const float*)d_in[11];
    const float* bd3 = (const float*)d_in[12];
    float* out = (float*)d_out;

    float* lat = nullptr; cudaGetSymbolAddress((void**)&lat, g_lat);
    float* rx  = nullptr; cudaGetSymbolAddress((void**)&rx,  g_rx);
    float* rl  = nullptr; cudaGetSymbolAddress((void**)&rl,  g_rl);
#define SYM(T, v, s) T* v = nullptr; cudaGetSymbolAddress((void**)&v, s)
    SYM(__nv_bfloat16, xh, g_xh);   SYM(__nv_bfloat16, xl, g_xl);
    SYM(__nv_bfloat16, lh, g_lh);   SYM(__nv_bfloat16, ll, g_ll);
    SYM(__nv_bfloat16, a1h, g_a1h); SYM(__nv_bfloat16, a1l, g_a1l);
    SYM(__nv_bfloat16, a2h, g_a2h); SYM(__nv_bfloat16, a2l, g_a2l);
    SYM(__nv_bfloat16, a4h, g_a4h); SYM(__nv_bfloat16, a4l, g_a4l);
    SYM(__nv_bfloat16, a5h, g_a5h); SYM(__nv_bfloat16, a5l, g_a5l);
    SYM(__nv_bfloat16, we1h, g_we1h); SYM(__nv_bfloat16, we1l, g_we1l);
    SYM(__nv_bfloat16, we2h, g_we2h); SYM(__nv_bfloat16, we2l, g_we2l);
    SYM(__nv_bfloat16, we3h, g_we3h); SYM(__nv_bfloat16, we3l, g_we3l);
    SYM(__nv_bfloat16, wd1h, g_wd1h); SYM(__nv_bfloat16, wd1l, g_wd1l);
    SYM(__nv_bfloat16, wd2h, g_wd2h); SYM(__nv_bfloat16, wd2l, g_wd2l);
    SYM(__nv_bfloat16, wd3h, g_wd3h); SYM(__nv_bfloat16, wd3l, g_wd3l);
#undef SYM

    zero_stats_kernel<<<1, 32>>>();

    // splits: x + all weights
#define CVT(src, dh, dl, rows, K) \
    convert_split_kernel<<<((rows) * (K) / 8 + 255) / 256, 256>>>(src, dh, dl, rows, K)
    CVT(x,   xh,   xl,   N_ROWS, DIM);
    CVT(We1, we1h, we1l, H1,  DIM);
    CVT(We2, we2h, we2l, H2,  H1);
    CVT(We3, we3h, we3l, LAT, H2);
    CVT(Wd1, wd1h, wd1l, H2,  LAT);
    CVT(Wd2, wd2h, wd2l, H1,  H2);
    CVT(Wd3, wd3h, wd3l, DIM, H1);
#undef CVT
    rownorm_kernel<<<N_ROWS, 256>>>(x, rx, DIM);

    const int dyn_smem = 2 * 65536 + 1024;
    cudaFuncSetAttribute(tc_gemm_bias_lrelu, cudaFuncAttributeMaxDynamicSharedMemorySize, dyn_smem);
    cudaFuncSetAttribute(dist_stats_tc_kernel, cudaFuncAttributeMaxDynamicSharedMemorySize, dyn_smem);

#define TCL(ah_, al_, wh_, wl_, b_, c_, oh_, ol_, N_, K_, wf, ws) \
    tc_gemm_bias_lrelu<<<dim3((N_) / 128, NB), 256, dyn_smem>>>( \
        ah_, al_, wh_, wl_, b_, c_, oh_, ol_, N_, (K_) / 64, wf, ws)
    // encoder
    TCL(xh,  xl,  we1h, we1l, be1, (float*)nullptr, a1h, a1l, H1,  DIM, 0, 1);
    TCL(a1h, a1l, we2h, we2l, be2, (float*)nullptr, a2h, a2l, H2,  H1,  0, 1);
    TCL(a2h, a2l, we3h, we3l, be3, lat,             lh,  ll,  LAT, H2,  1, 1);
    rownorm_kernel<<<N_ROWS, 128>>>(lat, rl, LAT);
    // decoder
    TCL(lh,  ll,  wd1h, wd1l, bd1, (float*)nullptr, a4h, a4l, H2,  LAT, 0, 1);
    TCL(a4h, a4l, wd2h, wd2l, bd2, (float*)nullptr, a5h, a5l, H1,  H2,  0, 1);
    TCL(a5h, a5l, wd3h, wd3l, bd3, out,  (__nv_bfloat16*)nullptr, (__nv_bfloat16*)nullptr, DIM, H1, 1, 0);
#undef TCL

    dist_stats_tc_kernel<<<NB * (NB + 1) / 2, 256, dyn_smem>>>(xh, xl, lh, ll, rx, rl);

    finalize_kernel<<<1, 1>>>(out, (long long)out_size - 1);
}

// round 7
// speedup vs baseline: 4.8000x; 1.0868x over previous
#include <cuda_runtime.h>
#include <cuda_bf16.h>
#include <math.h>
#include <stdint.h>

#define N_ROWS 4096
#define DIM    1024
#define H1     512
#define H2     256
#define LAT    128
#define SLOPE  0.01f
#define NB     (N_ROWS / 128)
#define NKC_X  (DIM / 64)
#define NKC_L  (LAT / 64)
#define TILE_ELEMS 8192
#define NCH_DIST (4 + NKC_X)        /* 4 latent pair-chunks + 16 x hi chunks */

#if defined(__CUDA_ARCH_FEAT_SM103_ALL) || defined(__CUDA_ARCH_FEAT_SM100_ALL) || defined(__CUDA_ARCH_FEAT_SM101_ALL)
#define HAS_TCGEN05 1
#else
#define HAS_TCGEN05 0
#endif

// -------- scratch --------
__device__ float g_lat[N_ROWS * LAT];
__device__ float g_rx[N_ROWS];
__device__ float g_rl[N_ROWS];
__device__ double g_stats[5];
__device__ __align__(16) __nv_bfloat16 g_xh[NB * NKC_X * TILE_ELEMS];
__device__ __align__(16) __nv_bfloat16 g_xl[NB * NKC_X * TILE_ELEMS];
__device__ __align__(16) __nv_bfloat16 g_lh[NB * NKC_L * TILE_ELEMS];
__device__ __align__(16) __nv_bfloat16 g_ll[NB * NKC_L * TILE_ELEMS];
__device__ __align__(16) __nv_bfloat16 g_a1h[N_ROWS * H1], g_a1l[N_ROWS * H1];
__device__ __align__(16) __nv_bfloat16 g_a2h[N_ROWS * H2], g_a2l[N_ROWS * H2];
__device__ __align__(16) __nv_bfloat16 g_a4h[N_ROWS * H2], g_a4l[N_ROWS * H2];
__device__ __align__(16) __nv_bfloat16 g_a5h[N_ROWS * H1], g_a5l[N_ROWS * H1];
__device__ __align__(16) __nv_bfloat16 g_we1h[H1 * DIM], g_we1l[H1 * DIM];
__device__ __align__(16) __nv_bfloat16 g_we2h[H2 * H1],  g_we2l[H2 * H1];
__device__ __align__(16) __nv_bfloat16 g_we3h[LAT * H2], g_we3l[LAT * H2];
__device__ __align__(16) __nv_bfloat16 g_wd1h[H2 * LAT], g_wd1l[H2 * LAT];
__device__ __align__(16) __nv_bfloat16 g_wd2h[H1 * H2],  g_wd2l[H1 * H2];
__device__ __align__(16) __nv_bfloat16 g_wd3h[DIM * H1], g_wd3l[DIM * H1];

__global__ void zero_stats_kernel() {
    if (threadIdx.x < 5) g_stats[threadIdx.x] = 0.0;
}

// ================= PTX helpers =================
__device__ __forceinline__ uint32_t smem_u32(const void* p) {
    uint32_t a;
    asm("{ .reg .u64 t; cvta.to.shared.u64 t, %1; cvt.u32.u64 %0, t; }" : "=r"(a) : "l"(p));
    return a;
}
__device__ __forceinline__ uint32_t elect_one() {
    uint32_t p;
    asm volatile("{\n\t.reg .pred p;\n\telect.sync _|p, 0xFFFFFFFF;\n\tselp.b32 %0, 1, 0, p;\n\t}" : "=r"(p));
    return p;
}
#define MBAR_INIT(mbar, c) \
    asm volatile("mbarrier.init.shared.b64 [%0], %1;" :: "r"(mbar), "r"((uint32_t)(c)) : "memory")
#define MBAR_INVAL(mbar) \
    asm volatile("mbarrier.inval.shared.b64 [%0];" :: "r"(mbar) : "memory")

__device__ __forceinline__ void mbar_wait_parity(uint32_t mbar, uint32_t parity) {
    uint32_t done;
    asm volatile("{\n\t.reg .pred p;\n\t"
                 "mbarrier.try_wait.parity.acquire.cta.shared::cta.b64 p, [%1], %2;\n\t"
                 "selp.b32 %0, 1, 0, p;\n\t}" : "=r"(done) : "r"(mbar), "r"(parity) : "memory");
    if (!done) {
        asm volatile("{\n\t.reg .pred P1;\n\t"
                     "WL_%=:\n\t"
                     "mbarrier.try_wait.parity.acquire.cta.shared::cta.b64 P1, [%0], %1, 0x989680;\n\t"
                     "@P1 bra.uni WD_%=;\n\t"
                     "bra.uni WL_%=;\n\t"
                     "WD_%=:\n\t}" :: "r"(mbar), "r"(parity) : "memory");
    }
}

#if HAS_TCGEN05
#define TC_ALLOC(smem_addr, n) \
    asm volatile("tcgen05.alloc.cta_group::1.sync.aligned.shared::cta.b32 [%0], %1;" \
                 :: "r"(smem_addr), "r"((uint32_t)(n)) : "memory")
#define TC_DEALLOC(tmem, n) \
    asm volatile("tcgen05.dealloc.cta_group::1.sync.aligned.b32 %0, %1;" :: "r"(tmem), "r"((uint32_t)(n)))
#define TC_COMMIT(mbar) \
    asm volatile("tcgen05.commit.cta_group::1.mbarrier::arrive::one.shared::cluster.b64 [%0];" \
                 :: "r"(mbar) : "memory")
#define TC_FENCE_AFTER()  asm volatile("tcgen05.fence::after_thread_sync;" ::: "memory")
#define TC_WAIT_LD()      asm volatile("tcgen05.wait::ld.sync.aligned;" ::: "memory")
#define FENCE_ASYNC()     asm volatile("fence.proxy.async.shared::cta;" ::: "memory")

__device__ __forceinline__ void mma_f16_ss(uint32_t d_tmem, uint64_t a_desc, uint64_t b_desc,
                                           uint32_t idesc, bool accum) {
    uint32_t en = accum ? 1u : 0u;
    asm volatile("{\n\t.reg .pred p;\n\t"
                 "setp.ne.u32 p, %5, 0;\n\t"
                 "tcgen05.mma.cta_group::1.kind::f16 [%0], %1, %2, %3, {%4, %4, %4, %4}, p;\n\t}"
                 :: "r"(d_tmem), "l"(a_desc), "l"(b_desc), "r"(idesc), "r"(0u), "r"(en)
                 : "memory");
}

#define LDTM32(r, addr) \
    asm volatile("tcgen05.ld.sync.aligned.32x32b.x32.b32 " \
        "{%0, %1, %2, %3, %4, %5, %6, %7, %8, %9, %10, %11, %12, %13, %14, %15, " \
        " %16, %17, %18, %19, %20, %21, %22, %23, %24, %25, %26, %27, %28, %29, %30, %31}, [%32];" \
        : "=r"((r)[0]), "=r"((r)[1]), "=r"((r)[2]), "=r"((r)[3]), \
          "=r"((r)[4]), "=r"((r)[5]), "=r"((r)[6]), "=r"((r)[7]), \
          "=r"((r)[8]), "=r"((r)[9]), "=r"((r)[10]), "=r"((r)[11]), \
          "=r"((r)[12]), "=r"((r)[13]), "=r"((r)[14]), "=r"((r)[15]), \
          "=r"((r)[16]), "=r"((r)[17]), "=r"((r)[18]), "=r"((r)[19]), \
          "=r"((r)[20]), "=r"((r)[21]), "=r"((r)[22]), "=r"((r)[23]), \
          "=r"((r)[24]), "=r"((r)[25]), "=r"((r)[26]), "=r"((r)[27]), \
          "=r"((r)[28]), "=r"((r)[29]), "=r"((r)[30]), "=r"((r)[31]) \
        : "r"(addr))

static __device__ __forceinline__ uint64_t make_desc(uint32_t addr) {
    const uint64_t base = (uint64_t(2) << 61) | (uint64_t(1) << 46)
                        | (uint64_t(64) << 32) | (uint64_t(1) << 16);
    return base | ((uint64_t)(addr >> 4) & 0x3FFF);
}
#define IDESC_128x128 0x8200490u
#endif // HAS_TCGEN05

// ================= row squared-norms =================
__global__ void rownorm_kernel(const float* __restrict__ X, float* __restrict__ r, int K) {
    int row = blockIdx.x;
    const float* p = X + (size_t)row * K;
    float s = 0.f;
    for (int k = threadIdx.x; k < K; k += blockDim.x) {
        float v = p[k];
        s += v * v;
    }
#pragma unroll
    for (int off = 16; off > 0; off >>= 1)
        s += __shfl_down_sync(0xffffffffu, s, off);
    __shared__ float sm[32];
    int lane = threadIdx.x & 31, wid = threadIdx.x >> 5;
    if (lane == 0) sm[wid] = s;
    __syncthreads();
    if (wid == 0) {
        int nw = blockDim.x >> 5;
        float v = (lane < nw) ? sm[lane] : 0.f;
#pragma unroll
        for (int off = 16; off > 0; off >>= 1)
            v += __shfl_down_sync(0xffffffffu, v, off);
        if (lane == 0) r[row] = v;
    }
}

// ================= fused split-convert (x + 6 weights in ONE launch) =================
struct alignas(16) bf16x8 { __nv_bfloat16 v[8]; };
struct CvtSeg { const float* src; __nv_bfloat16* dh; __nv_bfloat16* dl; int K; unsigned base; };
struct CvtArgs { CvtSeg seg[7]; unsigned total; };

__global__ void convert_all_kernel(CvtArgs args) {
    unsigned gid = blockIdx.x * blockDim.x + threadIdx.x;
    if (gid >= args.total) return;
    int si = 0;
#pragma unroll
    for (int i = 1; i < 7; i++)
        if (gid >= args.seg[i].base) si = i;
    const CvtSeg s = args.seg[si];
    unsigned idx = gid - s.base;
    int K = s.K, gpr = K >> 3, nkc = K >> 6;
    int r  = idx / gpr;
    int k0 = (idx - r * gpr) * 8;

    const float* p = s.src + (size_t)r * K + k0;
    float4 v0 = *(const float4*)p;
    float4 v1 = *(const float4*)(p + 4);
    float f[8] = {v0.x, v0.y, v0.z, v0.w, v1.x, v1.y, v1.z, v1.w};

    bf16x8 ph, pl;
#pragma unroll
    for (int m = 0; m < 8; m++) {
        __nv_bfloat16 h = __float2bfloat16(f[m]);
        ph.v[m] = h;
        pl.v[m] = __float2bfloat16(f[m] - __bfloat162float(h));
    }

    int rb = r >> 7, lr = r & 127;
    int kc = k0 >> 6, g = (k0 & 63) >> 3;
    int gsw = g ^ (lr & 7);
    size_t off = (((size_t)rb * nkc + kc) * 128 + lr) * 64 + gsw * 8;
    *(bf16x8*)&s.dh[off] = ph;
    *(bf16x8*)&s.dl[off] = pl;
}

// ================= tcgen05 GEMM + bias + LeakyReLU (unchanged from R6) =================
__global__ void __launch_bounds__(256, 1)
tc_gemm_bias_lrelu(const __nv_bfloat16* __restrict__ ah, const __nv_bfloat16* __restrict__ al,
                   const __nv_bfloat16* __restrict__ wh, const __nv_bfloat16* __restrict__ wl,
                   const float* __restrict__ bias,
                   float* __restrict__ Cfp,
                   __nv_bfloat16* __restrict__ oh, __nv_bfloat16* __restrict__ ol,
                   int N, int NC, int write_fp32, int write_split) {
    const int nb = blockIdx.x, mb = blockIdx.y;
    const int n0 = nb * 128, m0 = mb * 128;
    const int t = threadIdx.x;

#if HAS_TCGEN05
    extern __shared__ char dsm_raw[];
    char* dsm = (char*)(((uintptr_t)dsm_raw + 1023) & ~(uintptr_t)1023);
    __shared__ __align__(8) unsigned long long s_mbar[2];
    __shared__ uint32_t s_tmem;

    const int wid = t >> 5;
    const int lid = t & 31;
    const uint32_t mbar0 = smem_u32(&s_mbar[0]);
    const uint32_t mbar1 = mbar0 + 8;

    if (wid == 0) TC_ALLOC(smem_u32(&s_tmem), 128);
    if (t == 0) { MBAR_INIT(mbar0, 1); MBAR_INIT(mbar1, 1); }
    __syncthreads();
    const uint32_t D = s_tmem;
    const uint32_t smem_base = smem_u32(dsm);

#pragma unroll 1
    for (int n = 0; n < NC; n++) {
        if (n >= 2) {
            int c = n - 2;
            mbar_wait_parity((c & 1) ? mbar1 : mbar0, (uint32_t)((c >> 1) & 1));
        }
        char* buf = dsm + (size_t)(n & 1) * 65536;
        const uint4* srcs[4] = {
            (const uint4*)(ah + ((size_t)mb * NC + n) * TILE_ELEMS),
            (const uint4*)(al + ((size_t)mb * NC + n) * TILE_ELEMS),
            (const uint4*)(wh + ((size_t)nb * NC + n) * TILE_ELEMS),
            (const uint4*)(wl + ((size_t)nb * NC + n) * TILE_ELEMS)
        };
#pragma unroll
        for (int T = 0; T < 4; T++) {
            uint4* dst = (uint4*)(buf + T * 16384);
            const uint4* s = srcs[T];
#pragma unroll
            for (int w = 0; w < 4; w++)
                dst[t + w * 256] = s[t + w * 256];
        }
        FENCE_ASYNC();
        __syncthreads();

        if (wid == 0 && elect_one()) {
            uint32_t bufb = smem_base + (uint32_t)(n & 1) * 65536;
            uint64_t dAh = make_desc(bufb);
            uint64_t dAl = make_desc(bufb + 16384);
            uint64_t dWh = make_desc(bufb + 32768);
            uint64_t dWl = make_desc(bufb + 49152);
            bool first = (n == 0);
#pragma unroll
            for (int s = 0; s < 4; s++) {
                uint64_t off = s * 2;
                mma_f16_ss(D, dAh + off, dWh + off, IDESC_128x128, !(first && s == 0));
                mma_f16_ss(D, dAh + off, dWl + off, IDESC_128x128, true);
                mma_f16_ss(D, dAl + off, dWh + off, IDESC_128x128, true);
            }
            TC_COMMIT((n & 1) ? mbar1 : mbar0);
        }
    }
    {
        int c0 = (NC >= 2) ? NC - 2 : 0;
        for (int c = c0; c < NC; c++)
            mbar_wait_parity((c & 1) ? mbar1 : mbar0, (uint32_t)((c >> 1) & 1));
    }
    TC_FENCE_AFTER();

    const int wg  = wid >> 2;
    const int sub = wid & 3;
    const int lr  = sub * 32 + lid;
    const int m   = m0 + lr;
    const int nkc_out = N >> 6;

#pragma unroll
    for (int bb = 0; bb < 2; bb++) {
        const int colbase = wg * 64 + bb * 32;
        uint32_t dr[32];
        LDTM32(dr, D + colbase);
        TC_WAIT_LD();
        float v[32];
#pragma unroll
        for (int c = 0; c < 32; c++) {
            float x = __uint_as_float(dr[c]) + __ldg(&bias[n0 + colbase + c]);
            v[c] = (x >= 0.f) ? x : SLOPE * x;
        }
        if (write_fp32) {
#pragma unroll
            for (int c = 0; c < 32; c++)
                Cfp[(size_t)m * N + n0 + colbase + c] = v[c];
        }
        if (write_split) {
#pragma unroll
            for (int g8 = 0; g8 < 4; g8++) {
                int nn = n0 + colbase + g8 * 8;
                int kc = nn >> 6, g = (nn & 63) >> 3;
                int gsw = g ^ (lr & 7);
                size_t off = (((size_t)mb * nkc_out + kc) * 128 + lr) * 64 + gsw * 8;
                bf16x8 ph, pl;
#pragma unroll
                for (int e = 0; e < 8; e++) {
                    float x = v[g8 * 8 + e];
                    __nv_bfloat16 h = __float2bfloat16(x);
                    ph.v[e] = h;
                    pl.v[e] = __float2bfloat16(x - __bfloat162float(h));
                }
                *(bf16x8*)&oh[off] = ph;
                *(bf16x8*)&ol[off] = pl;
            }
        }
    }

    __syncthreads();
    if (t == 0) { MBAR_INVAL(mbar0); MBAR_INVAL(mbar1); }
    __syncthreads();
    if (wid == 0) TC_DEALLOC(D, 128);

#else
    const int K = NC * 64;
    const int lr0 = t & 127;
    const int m = m0 + lr0;
    const int jh = (t >> 7) * 64;
    const int nkc_out = N >> 6;
    for (int jj = 0; jj < 64; jj++) {
        int nn = n0 + jh + jj;
        int wrb = nn >> 7, wlr = nn & 127;
        float acc = 0.f;
        for (int k = 0; k < K; k++) {
            int kc = k >> 6, g = (k & 63) >> 3, e = k & 7;
            size_t aoff = (((size_t)mb * NC + kc) * 128 + lr0) * 64 + (size_t)((g ^ (lr0 & 7)) * 8 + e);
            size_t woff = (((size_t)wrb * NC + kc) * 128 + wlr) * 64 + (size_t)((g ^ (wlr & 7)) * 8 + e);
            float av = __bfloat162float(ah[aoff]) + __bfloat162float(al[aoff]);
            float wv = __bfloat162float(wh[woff]) + __bfloat162float(wl[woff]);
            acc += av * wv;
        }
        float x = acc + bias[nn];
        x = (x >= 0.f) ? x : SLOPE * x;
        if (write_fp32) Cfp[(size_t)m * N + nn] = x;
        if (write_split) {
            __nv_bfloat16 h = __float2bfloat16(x);
            int kc = nn >> 6, g = (nn & 63) >> 3;
            size_t off = (((size_t)mb * nkc_out + kc) * 128 + lr0) * 64 + (size_t)((g ^ (lr0 & 7)) * 8 + (nn & 7));
            oh[off] = h;
            ol[off] = __float2bfloat16(x - __bfloat162float(h));
        }
    }
#endif
}

// ================= fused Gram + distance + stats, v3 =================
// x Gram: hi-only bf16 (error ~3e-5 on distances). latent: full hi/lo split.
// 32KB pair-chunk buffers -> smem 66KB -> occupancy 2. 20 chunks:
//   n=0..3: latent (kc = n>>1; hi if n even in buf0, lo if n odd in buf1)
//   n=4..19: x hi chunk kc = n-4, buf = n&1
__global__ void __launch_bounds__(256, 2)
dist_stats_tc_kernel(const __nv_bfloat16* __restrict__ xh,
                     const __nv_bfloat16* __restrict__ xl,
                     const __nv_bfloat16* __restrict__ lh,
                     const __nv_bfloat16* __restrict__ ll,
                     const float* __restrict__ rx,
                     const float* __restrict__ rl) {
    int b = blockIdx.x;
    int bi = 0, rem = b;
    while (rem >= NB - bi) { rem -= NB - bi; bi++; }
    int bj = bi + rem;
    const bool diag = (bi == bj);
    const int i0 = bi * 128, j0 = bj * 128;

    __shared__ double red[256];
    const int t = threadIdx.x;

    float fs1 = 0.f, fs2 = 0.f, fs11 = 0.f, fs22 = 0.f, fs12 = 0.f;

#if HAS_TCGEN05
    extern __shared__ char dsm_raw[];
    char* dsm = (char*)(((uintptr_t)dsm_raw + 1023) & ~(uintptr_t)1023);
    __shared__ __align__(8) unsigned long long s_mbar[2];
    __shared__ uint32_t s_tmem;

    const int wid = t >> 5;
    const int lid = t & 31;
    const uint32_t mbar0 = smem_u32(&s_mbar[0]);
    const uint32_t mbar1 = mbar0 + 8;

    if (wid == 0) TC_ALLOC(smem_u32(&s_tmem), 256);
    if (t == 0) { MBAR_INIT(mbar0, 1); MBAR_INIT(mbar1, 1); }
    __syncthreads();
    const uint32_t tmem = s_tmem;
    const uint32_t D_X = tmem, D_L = tmem + 128;
    const uint32_t smem_base = smem_u32(dsm);

    // Commit schedule: n==1,3 -> mbar1 (3 latent MMAs); n>=4 -> mbar(n&1).
    // Wait-for-chunk-p mapping (consumer commit of chunk p's buffer):
    //   p<4         -> mbar1, idx = p>>1
    //   p odd >=5   -> mbar1, idx = (p-1)>>1
    //   p even >=4  -> mbar0, idx = (p-4)>>1
    // Waits occur strictly in schedule order, so phase-count floors are
    // established by prior waits -> parity (idx&1) is unambiguous.
#pragma unroll 1
    for (int n = 0; n < NCH_DIST; n++) {
        if (n >= 2) {
            int p = n - 2;
            uint32_t m; int idx;
            if (p < 4)      { m = mbar1; idx = p >> 1; }
            else if (p & 1) { m = mbar1; idx = (p - 1) >> 1; }
            else            { m = mbar0; idx = (p - 4) >> 1; }
            mbar_wait_parity(m, (uint32_t)(idx & 1));
        }

        const __nv_bfloat16 *srcA, *srcB;
        if (n < 4) {
            int kc = n >> 1;
            const __nv_bfloat16* s = (n & 1) ? ll : lh;
            srcA = s + ((size_t)bi * NKC_L + kc) * TILE_ELEMS;
            srcB = s + ((size_t)bj * NKC_L + kc) * TILE_ELEMS;
        } else {
            int kc = n - 4;
            srcA = xh + ((size_t)bi * NKC_X + kc) * TILE_ELEMS;
            srcB = xh + ((size_t)bj * NKC_X + kc) * TILE_ELEMS;
        }
        {
            uint4* dst = (uint4*)(dsm + (size_t)(n & 1) * 32768);
            const uint4* sA = (const uint4*)srcA;
            const uint4* sB = (const uint4*)srcB;
#pragma unroll
            for (int w = 0; w < 4; w++) dst[t + w * 256] = sA[t + w * 256];
#pragma unroll
            for (int w = 0; w < 4; w++) dst[1024 + t + w * 256] = sB[t + w * 256];
        }
        FENCE_ASYNC();
        __syncthreads();

        if (wid == 0 && elect_one()) {
            if (n >= 4) {
                uint32_t bufb = smem_base + (uint32_t)(n & 1) * 32768;
                uint64_t dA = make_desc(bufb), dB = make_desc(bufb + 16384);
#pragma unroll
                for (int s = 0; s < 4; s++)
                    mma_f16_ss(D_X, dA + s * 2, dB + s * 2, IDESC_128x128, !(n == 4 && s == 0));
                TC_COMMIT((n & 1) ? mbar1 : mbar0);
            } else if (n & 1) {
                uint32_t b0 = smem_base, b1 = smem_base + 32768;
                uint64_t dAh = make_desc(b0), dBh = make_desc(b0 + 16384);
                uint64_t dAl = make_desc(b1), dBl = make_desc(b1 + 16384);
#pragma unroll
                for (int s = 0; s < 4; s++) {
                    uint64_t off = s * 2;
                    mma_f16_ss(D_L, dAh + off, dBh + off, IDESC_128x128, !(n == 1 && s == 0));
                    mma_f16_ss(D_L, dAh + off, dBl + off, IDESC_128x128, true);
                    mma_f16_ss(D_L, dAl + off, dBh + off, IDESC_128x128, true);
                }
                TC_COMMIT(mbar1);
            }
        }
    }

    // drain: last mbar0 commit = chunk18 -> idx 7 (parity 1);
    //        last mbar1 commit = chunk19 -> idx 9 (parity 1).
    mbar_wait_parity(mbar0, 1u);
    mbar_wait_parity(mbar1, 1u);
    TC_FENCE_AFTER();

    const int wg  = wid >> 2;
    const int sub = wid & 3;
    const int i = i0 + sub * 32 + lid;
    const float rxi = __ldg(&rx[i]);
    const float rli = __ldg(&rl[i]);

#pragma unroll
    for (int bb = 0; bb < 2; bb++) {
        const int colbase = wg * 64 + bb * 32;
        uint32_t xg[32], lg[32];
        LDTM32(xg, D_X + colbase);
        LDTM32(lg, D_L + colbase);
        TC_WAIT_LD();
#pragma unroll
        for (int c = 0; c < 32; c++) {
            int j = j0 + colbase + c;
            if (!diag || j > i) {
                float gx = __uint_as_float(xg[c]);
                float gl = __uint_as_float(lg[c]);
                float sqx = rxi + __ldg(&rx[j]) - 2.f * gx;
                float sql = rli + __ldg(&rl[j]) - 2.f * gl;
                float dx = sqrtf(fmaxf(sqx, 0.f));
                float dv = sqrtf(fmaxf(sql, 0.f));
                fs1  += dx;
                fs2  += dv;
                fs11 += dx * dx;
                fs22 += dv * dv;
                fs12 += dx * dv;
            }
        }
    }

    __syncthreads();
    if (t == 0) { MBAR_INVAL(mbar0); MBAR_INVAL(mbar1); }
    __syncthreads();
    if (wid == 0) TC_DEALLOC(tmem, 256);

#else  // fallback: dequant fp32 (correct; never the selected cubin on GB300)
    const int tx8  = (t & 15) * 8;
    const int ty8  = (t >> 4) * 8;
    for (int ii = 0; ii < 8; ii++) {
        int i = i0 + ty8 + ii;
        float rxi = rx[i], rli = rl[i];
        int ib = i >> 7, ilr = i & 127;
        for (int jj = 0; jj < 8; jj++) {
            int j = j0 + tx8 + jj;
            if (diag && j <= i) continue;
            int jb = j >> 7, jlr = j & 127;
            float gx = 0.f, gl = 0.f;
            for (int k = 0; k < DIM; k++) {
                int kc = k >> 6, g = (k & 63) >> 3, e = k & 7;
                size_t ioff = (((size_t)ib * NKC_X + kc) * 128 + ilr) * 64 + (size_t)((g ^ (ilr & 7)) * 8 + e);
                size_t joff = (((size_t)jb * NKC_X + kc) * 128 + jlr) * 64 + (size_t)((g ^ (jlr & 7)) * 8 + e);
                gx += (__bfloat162float(xh[ioff]) + __bfloat162float(xl[ioff]))
                    * (__bfloat162float(xh[joff]) + __bfloat162float(xl[joff]));
            }
            for (int k = 0; k < LAT; k++) {
                int kc = k >> 6, g = (k & 63) >> 3, e = k & 7;
                size_t ioff = (((size_t)ib * NKC_L + kc) * 128 + ilr) * 64 + (size_t)((g ^ (ilr & 7)) * 8 + e);
                size_t joff = (((size_t)jb * NKC_L + kc) * 128 + jlr) * 64 + (size_t)((g ^ (jlr & 7)) * 8 + e);
                gl += (__bfloat162float(lh[ioff]) + __bfloat162float(ll[ioff]))
                    * (__bfloat162float(lh[joff]) + __bfloat162float(ll[joff]));
            }
            float dx = sqrtf(fmaxf(rxi + rx[j] - 2.f * gx, 0.f));
            float dv = sqrtf(fmaxf(rli + rl[j] - 2.f * gl, 0.f));
            fs1 += dx; fs2 += dv; fs11 += dx * dx; fs22 += dv * dv; fs12 += dx * dv;
        }
    }
#endif

    float vals[5] = {fs1, fs2, fs11, fs22, fs12};
#pragma unroll
    for (int v = 0; v < 5; v++) {
        red[t] = (double)vals[v];
        __syncthreads();
        for (int off = 128; off > 0; off >>= 1) {
            if (t < off) red[t] += red[t + off];
            __syncthreads();
        }
        if (t == 0) atomicAdd(&g_stats[v], red[0]);
        __syncthreads();
    }
}

__global__ void finalize_kernel(float* __restrict__ out, long long idx) {
    const double n = (double)N_ROWS * (double)N_ROWS;
    double s1  = 2.0 * g_stats[0];
    double s2  = 2.0 * g_stats[1];
    double s11 = 2.0 * g_stats[2];
    double s22 = 2.0 * g_stats[3];
    double s12 = 2.0 * g_stats[4];
    double m1 = s1 / n;
    double m2 = s2 / n;
    double v1 = (s11 - n * m1 * m1) / (n - 1.0);
    double v2 = (s22 - n * m2 * m2) / (n - 1.0);
    double cov = s12 / n - m1 * m2;
    out[idx] = (float)(cov / sqrt(v1 * v2));
}

extern "C" void kernel_launch(void* const* d_in, const int* in_sizes, int n_in,
                              void* d_out, int out_size) {
    const float* x   = (const float*)d_in[0];
    const float* We1 = (const float*)d_in[1];
    const float* be1 = (const float*)d_in[2];
    const float* We2 = (const float*)d_in[3];
    const float* be2 = (const float*)d_in[4];
    const float* We3 = (const float*)d_in[5];
    const float* be3 = (const float*)d_in[6];
    const float* Wd1 = (const float*)d_in[7];
    const float* bd1 = (const float*)d_in[8];
    const float* Wd2 = (const float*)d_in[9];
    const float* bd2 = (const float*)d_in[10];
    const float* Wd3 = (const float*)d_in[11];
    const float* bd3 = (const float*)d_in[12];
    float* out = (float*)d_out;

    float* lat = nullptr; cudaGetSymbolAddress((void**)&lat, g_lat);
    float* rx  = nullptr; cudaGetSymbolAddress((void**)&rx,  g_rx);
    float* rl  = nullptr; cudaGetSymbolAddress((void**)&rl,  g_rl);
#define SYM(T, v, s) T* v = nullptr; cudaGetSymbolAddress((void**)&v, s)
    SYM(__nv_bfloat16, xh, g_xh);   SYM(__nv_bfloat16, xl, g_xl);
    SYM(__nv_bfloat16, lh, g_lh);   SYM(__nv_bfloat16, ll, g_ll);
    SYM(__nv_bfloat16, a1h, g_a1h); SYM(__nv_bfloat16, a1l, g_a1l);
    SYM(__nv_bfloat16, a2h, g_a2h); SYM(__nv_bfloat16, a2l, g_a2l);
    SYM(__nv_bfloat16, a4h, g_a4h); SYM(__nv_bfloat16, a4l, g_a4l);
    SYM(__nv_bfloat16, a5h, g_a5h); SYM(__nv_bfloat16, a5l, g_a5l);
    SYM(__nv_bfloat16, we1h, g_we1h); SYM(__nv_bfloat16, we1l, g_we1l);
    SYM(__nv_bfloat16, we2h, g_we2h); SYM(__nv_bfloat16, we2l, g_we2l);
    SYM(__nv_bfloat16, we3h, g_we3h); SYM(__nv_bfloat16, we3l, g_we3l);
    SYM(__nv_bfloat16, wd1h, g_wd1h); SYM(__nv_bfloat16, wd1l, g_wd1l);
    SYM(__nv_bfloat16, wd2h, g_wd2h); SYM(__nv_bfloat16, wd2l, g_wd2l);
    SYM(__nv_bfloat16, wd3h, g_wd3h); SYM(__nv_bfloat16, wd3l, g_wd3l);
#undef SYM

    zero_stats_kernel<<<1, 32>>>();

    // one fused convert for x + all weights
    {
        CvtArgs a;
        unsigned base = 0;
        auto set = [&](int i, const float* src, __nv_bfloat16* dh, __nv_bfloat16* dl,
                       int rows, int K) {
            a.seg[i] = {src, dh, dl, K, base};
            base += (unsigned)(rows * K / 8);
        };
        set(0, x,   xh,   xl,   N_ROWS, DIM);
        set(1, We1, we1h, we1l, H1,  DIM);
        set(2, We2, we2h, we2l, H2,  H1);
        set(3, We3, we3h, we3l, LAT, H2);
        set(4, Wd1, wd1h, wd1l, H2,  LAT);
        set(5, Wd2, wd2h, wd2l, H1,  H2);
        set(6, Wd3, wd3h, wd3l, DIM, H1);
        a.total = base;
        convert_all_kernel<<<(base + 255) / 256, 256>>>(a);
    }
    rownorm_kernel<<<N_ROWS, 256>>>(x, rx, DIM);

    const int smem_gemm = 2 * 65536 + 1024;
    const int smem_dist = 2 * 32768 + 1024;
    cudaFuncSetAttribute(tc_gemm_bias_lrelu, cudaFuncAttributeMaxDynamicSharedMemorySize, smem_gemm);
    cudaFuncSetAttribute(dist_stats_tc_kernel, cudaFuncAttributeMaxDynamicSharedMemorySize, smem_dist);

#define TCL(ah_, al_, wh_, wl_, b_, c_, oh_, ol_, N_, K_, wf, ws) \
    tc_gemm_bias_lrelu<<<dim3((N_) / 128, NB), 256, smem_gemm>>>( \
        ah_, al_, wh_, wl_, b_, c_, oh_, ol_, N_, (K_) / 64, wf, ws)
    TCL(xh,  xl,  we1h, we1l, be1, (float*)nullptr, a1h, a1l, H1,  DIM, 0, 1);
    TCL(a1h, a1l, we2h, we2l, be2, (float*)nullptr, a2h, a2l, H2,  H1,  0, 1);
    TCL(a2h, a2l, we3h, we3l, be3, lat,             lh,  ll,  LAT, H2,  1, 1);
    rownorm_kernel<<<N_ROWS, 128>>>(lat, rl, LAT);
    TCL(lh,  ll,  wd1h, wd1l, bd1, (float*)nullptr, a4h, a4l, H2,  LAT, 0, 1);
    TCL(a4h, a4l, wd2h, wd2l, bd2, (float*)nullptr, a5h, a5l, H1,  H2,  0, 1);
    TCL(a5h, a5l, wd3h, wd3l, bd3, out,  (__nv_bfloat16*)nullptr, (__nv_bfloat16*)nullptr, DIM, H1, 1, 0);
#undef TCL

    dist_stats_tc_kernel<<<NB * (NB + 1) / 2, 256, smem_dist>>>(xh, xl, lh, ll, rx, rl);

    finalize_kernel<<<1, 1>>>(out, (long long)out_size - 1);
}

// round 8
// speedup vs baseline: 4.9649x; 1.0343x over previous
#include <cuda_runtime.h>
#include <cuda_bf16.h>
#include <math.h>
#include <stdint.h>

#define N_ROWS 4096
#define DIM    1024
#define H1     512
#define H2     256
#define LAT    128
#define SLOPE  0.01f
#define NB     (N_ROWS / 128)
#define NKC_X  (DIM / 64)
#define NKC_L  (LAT / 64)
#define TILE_ELEMS 8192
#define TILE_BYTES 16384
#define NCH_DIST (4 + NKC_X)

#if defined(__CUDA_ARCH_FEAT_SM103_ALL) || defined(__CUDA_ARCH_FEAT_SM100_ALL) || defined(__CUDA_ARCH_FEAT_SM101_ALL)
#define HAS_TCGEN05 1
#else
#define HAS_TCGEN05 0
#endif

// -------- scratch --------
__device__ float g_lat[N_ROWS * LAT];
__device__ float g_rx[N_ROWS];
__device__ float g_rl[N_ROWS];
__device__ double g_stats[5];
__device__ __align__(16) __nv_bfloat16 g_xh[NB * NKC_X * TILE_ELEMS];
__device__ __align__(16) __nv_bfloat16 g_xl[NB * NKC_X * TILE_ELEMS];
__device__ __align__(16) __nv_bfloat16 g_lh[NB * NKC_L * TILE_ELEMS];
__device__ __align__(16) __nv_bfloat16 g_ll[NB * NKC_L * TILE_ELEMS];
__device__ __align__(16) __nv_bfloat16 g_a1h[N_ROWS * H1], g_a1l[N_ROWS * H1];
__device__ __align__(16) __nv_bfloat16 g_a2h[N_ROWS * H2], g_a2l[N_ROWS * H2];
__device__ __align__(16) __nv_bfloat16 g_a4h[N_ROWS * H2], g_a4l[N_ROWS * H2];
__device__ __align__(16) __nv_bfloat16 g_a5h[N_ROWS * H1], g_a5l[N_ROWS * H1];
__device__ __align__(16) __nv_bfloat16 g_we1h[H1 * DIM], g_we1l[H1 * DIM];
__device__ __align__(16) __nv_bfloat16 g_we2h[H2 * H1],  g_we2l[H2 * H1];
__device__ __align__(16) __nv_bfloat16 g_we3h[LAT * H2], g_we3l[LAT * H2];
__device__ __align__(16) __nv_bfloat16 g_wd1h[H2 * LAT], g_wd1l[H2 * LAT];
__device__ __align__(16) __nv_bfloat16 g_wd2h[H1 * H2],  g_wd2l[H1 * H2];
__device__ __align__(16) __nv_bfloat16 g_wd3h[DIM * H1], g_wd3l[DIM * H1];

__global__ void zero_stats_kernel() {
    if (threadIdx.x < 5) g_stats[threadIdx.x] = 0.0;
}

// ================= PTX helpers =================
__device__ __forceinline__ uint32_t smem_u32(const void* p) {
    uint32_t a;
    asm("{ .reg .u64 t; cvta.to.shared.u64 t, %1; cvt.u32.u64 %0, t; }" : "=r"(a) : "l"(p));
    return a;
}
__device__ __forceinline__ uint32_t elect_one() {
    uint32_t p;
    asm volatile("{\n\t.reg .pred p;\n\telect.sync _|p, 0xFFFFFFFF;\n\tselp.b32 %0, 1, 0, p;\n\t}" : "=r"(p));
    return p;
}
#define MBAR_INIT(mbar, c) \
    asm volatile("mbarrier.init.shared.b64 [%0], %1;" :: "r"(mbar), "r"((uint32_t)(c)) : "memory")
#define MBAR_INVAL(mbar) \
    asm volatile("mbarrier.inval.shared.b64 [%0];" :: "r"(mbar) : "memory")
#define MBAR_ARRIVE(mbar) \
    asm volatile("mbarrier.arrive.shared.b64 _, [%0];" :: "r"(mbar) : "memory")
#define MBAR_EXPECT_TX(mbar, bytes) \
    asm volatile("mbarrier.arrive.expect_tx.shared.b64 _, [%0], %1;" \
                 :: "r"(mbar), "r"((uint32_t)(bytes)) : "memory")

__device__ __forceinline__ void mbar_wait_parity(uint32_t mbar, uint32_t parity) {
    uint32_t done;
    asm volatile("{\n\t.reg .pred p;\n\t"
                 "mbarrier.try_wait.parity.acquire.cta.shared::cta.b64 p, [%1], %2;\n\t"
                 "selp.b32 %0, 1, 0, p;\n\t}" : "=r"(done) : "r"(mbar), "r"(parity) : "memory");
    if (!done) {
        asm volatile("{\n\t.reg .pred P1;\n\t"
                     "WL_%=:\n\t"
                     "mbarrier.try_wait.parity.acquire.cta.shared::cta.b64 P1, [%0], %1, 0x989680;\n\t"
                     "@P1 bra.uni WD_%=;\n\t"
                     "bra.uni WL_%=;\n\t"
                     "WD_%=:\n\t}" :: "r"(mbar), "r"(parity) : "memory");
    }
}

#if HAS_TCGEN05
#define TC_ALLOC(smem_addr, n) \
    asm volatile("tcgen05.alloc.cta_group::1.sync.aligned.shared::cta.b32 [%0], %1;" \
                 :: "r"(smem_addr), "r"((uint32_t)(n)) : "memory")
#define TC_DEALLOC(tmem, n) \
    asm volatile("tcgen05.dealloc.cta_group::1.sync.aligned.b32 %0, %1;" :: "r"(tmem), "r"((uint32_t)(n)))
#define TC_COMMIT(mbar) \
    asm volatile("tcgen05.commit.cta_group::1.mbarrier::arrive::one.shared::cluster.b64 [%0];" \
                 :: "r"(mbar) : "memory")
#define TC_FENCE_AFTER()  asm volatile("tcgen05.fence::after_thread_sync;" ::: "memory")
#define TC_WAIT_LD()      asm volatile("tcgen05.wait::ld.sync.aligned;" ::: "memory")
#define BULK_G2S(dst, src, bytes, mbar) \
    asm volatile("cp.async.bulk.shared::cta.global.mbarrier::complete_tx::bytes [%0], [%1], %2, [%3];" \
                 :: "r"(dst), "l"(src), "r"((uint32_t)(bytes)), "r"(mbar) : "memory")

__device__ __forceinline__ void mma_f16_ss(uint32_t d_tmem, uint64_t a_desc, uint64_t b_desc,
                                           uint32_t idesc, bool accum) {
    uint32_t en = accum ? 1u : 0u;
    asm volatile("{\n\t.reg .pred p;\n\t"
                 "setp.ne.u32 p, %5, 0;\n\t"
                 "tcgen05.mma.cta_group::1.kind::f16 [%0], %1, %2, %3, {%4, %4, %4, %4}, p;\n\t}"
                 :: "r"(d_tmem), "l"(a_desc), "l"(b_desc), "r"(idesc), "r"(0u), "r"(en)
                 : "memory");
}

#define LDTM32(r, addr) \
    asm volatile("tcgen05.ld.sync.aligned.32x32b.x32.b32 " \
        "{%0, %1, %2, %3, %4, %5, %6, %7, %8, %9, %10, %11, %12, %13, %14, %15, " \
        " %16, %17, %18, %19, %20, %21, %22, %23, %24, %25, %26, %27, %28, %29, %30, %31}, [%32];" \
        : "=r"((r)[0]), "=r"((r)[1]), "=r"((r)[2]), "=r"((r)[3]), \
          "=r"((r)[4]), "=r"((r)[5]), "=r"((r)[6]), "=r"((r)[7]), \
          "=r"((r)[8]), "=r"((r)[9]), "=r"((r)[10]), "=r"((r)[11]), \
          "=r"((r)[12]), "=r"((r)[13]), "=r"((r)[14]), "=r"((r)[15]), \
          "=r"((r)[16]), "=r"((r)[17]), "=r"((r)[18]), "=r"((r)[19]), \
          "=r"((r)[20]), "=r"((r)[21]), "=r"((r)[22]), "=r"((r)[23]), \
          "=r"((r)[24]), "=r"((r)[25]), "=r"((r)[26]), "=r"((r)[27]), \
          "=r"((r)[28]), "=r"((r)[29]), "=r"((r)[30]), "=r"((r)[31]) \
        : "r"(addr))

static __device__ __forceinline__ uint64_t make_desc(uint32_t addr) {
    const uint64_t base = (uint64_t(2) << 61) | (uint64_t(1) << 46)
                        | (uint64_t(64) << 32) | (uint64_t(1) << 16);
    return base | ((uint64_t)(addr >> 4) & 0x3FFF);
}
#define IDESC_128x128 0x8200490u
#endif // HAS_TCGEN05

// ================= row squared-norms =================
__global__ void rownorm_kernel(const float* __restrict__ X, float* __restrict__ r, int K) {
    int row = blockIdx.x;
    const float* p = X + (size_t)row * K;
    float s = 0.f;
    for (int k = threadIdx.x; k < K; k += blockDim.x) {
        float v = p[k];
        s += v * v;
    }
#pragma unroll
    for (int off = 16; off > 0; off >>= 1)
        s += __shfl_down_sync(0xffffffffu, s, off);
    __shared__ float sm[32];
    int lane = threadIdx.x & 31, wid = threadIdx.x >> 5;
    if (lane == 0) sm[wid] = s;
    __syncthreads();
    if (wid == 0) {
        int nw = blockDim.x >> 5;
        float v = (lane < nw) ? sm[lane] : 0.f;
#pragma unroll
        for (int off = 16; off > 0; off >>= 1)
            v += __shfl_down_sync(0xffffffffu, v, off);
        if (lane == 0) r[row] = v;
    }
}

// ================= fused split-convert =================
struct alignas(16) bf16x8 { __nv_bfloat16 v[8]; };
struct CvtSeg { const float* src; __nv_bfloat16* dh; __nv_bfloat16* dl; int K; unsigned base; };
struct CvtArgs { CvtSeg seg[7]; unsigned total; };

__global__ void convert_all_kernel(CvtArgs args) {
    unsigned gid = blockIdx.x * blockDim.x + threadIdx.x;
    if (gid >= args.total) return;
    int si = 0;
#pragma unroll
    for (int i = 1; i < 7; i++)
        if (gid >= args.seg[i].base) si = i;
    const CvtSeg s = args.seg[si];
    unsigned idx = gid - s.base;
    int K = s.K, gpr = K >> 3, nkc = K >> 6;
    int r  = idx / gpr;
    int k0 = (idx - r * gpr) * 8;

    const float* p = s.src + (size_t)r * K + k0;
    float4 v0 = *(const float4*)p;
    float4 v1 = *(const float4*)(p + 4);
    float f[8] = {v0.x, v0.y, v0.z, v0.w, v1.x, v1.y, v1.z, v1.w};

    bf16x8 ph, pl;
#pragma unroll
    for (int m = 0; m < 8; m++) {
        __nv_bfloat16 h = __float2bfloat16(f[m]);
        ph.v[m] = h;
        pl.v[m] = __float2bfloat16(f[m] - __bfloat162float(h));
    }

    int rb = r >> 7, lr = r & 127;
    int kc = k0 >> 6, g = (k0 & 63) >> 3;
    int gsw = g ^ (lr & 7);
    size_t off = (((size_t)rb * nkc + kc) * 128 + lr) * 64 + gsw * 8;
    *(bf16x8*)&s.dh[off] = ph;
    *(bf16x8*)&s.dl[off] = pl;
}

// ================= tcgen05 GEMM + bias + LeakyReLU, async-bulk pipeline =================
__global__ void __launch_bounds__(256, 1)
tc_gemm_bias_lrelu(const __nv_bfloat16* __restrict__ ah, const __nv_bfloat16* __restrict__ al,
                   const __nv_bfloat16* __restrict__ wh, const __nv_bfloat16* __restrict__ wl,
                   const float* __restrict__ bias,
                   float* __restrict__ Cfp,
                   __nv_bfloat16* __restrict__ oh, __nv_bfloat16* __restrict__ ol,
                   int N, int NC, int write_fp32, int write_split) {
    const int nb = blockIdx.x, mb = blockIdx.y;
    const int n0 = nb * 128, m0 = mb * 128;
    const int t = threadIdx.x;

#if HAS_TCGEN05
    extern __shared__ char dsm_raw[];
    char* dsm = (char*)(((uintptr_t)dsm_raw + 1023) & ~(uintptr_t)1023);
    __shared__ __align__(8) unsigned long long s_mbar[5];
    __shared__ uint32_t s_tmem;

    const int wid = t >> 5;
    const int lid = t & 31;
    const uint32_t full0  = smem_u32(&s_mbar[0]);
    const uint32_t full1  = full0 + 8;
    const uint32_t empty0 = full0 + 16;
    const uint32_t empty1 = full0 + 24;
    const uint32_t donem  = full0 + 32;

    if (wid == 0) TC_ALLOC(smem_u32(&s_tmem), 128);
    if (t == 0) {
        MBAR_INIT(full0, 1);  MBAR_INIT(full1, 1);
        MBAR_INIT(empty0, 1); MBAR_INIT(empty1, 1);
        MBAR_INIT(donem, 1);
    }
    __syncthreads();
    const uint32_t D = s_tmem;
    const uint32_t smem_base = smem_u32(dsm);

    if (wid == 0 && elect_one()) {
        // single-driver pipeline; per-barrier waits in consecutive-index order
        // anchor the phase-count floor (parity-safe).
#pragma unroll 1
        for (int n = 0; n < NC; n++) {
            const int b = n & 1;
            const uint32_t fb = b ? full1 : full0;
            const uint32_t eb = b ? empty1 : empty0;
            if (n >= 2) mbar_wait_parity(eb, (uint32_t)(((n - 2) >> 1) & 1));

            const uint32_t bufb = smem_base + (uint32_t)b * 65536;
            MBAR_EXPECT_TX(fb, 65536);
            BULK_G2S(bufb,         (const char*)(ah + ((size_t)mb * NC + n) * TILE_ELEMS), TILE_BYTES, fb);
            BULK_G2S(bufb + 16384, (const char*)(al + ((size_t)mb * NC + n) * TILE_ELEMS), TILE_BYTES, fb);
            BULK_G2S(bufb + 32768, (const char*)(wh + ((size_t)nb * NC + n) * TILE_ELEMS), TILE_BYTES, fb);
            BULK_G2S(bufb + 49152, (const char*)(wl + ((size_t)nb * NC + n) * TILE_ELEMS), TILE_BYTES, fb);
            mbar_wait_parity(fb, (uint32_t)((n >> 1) & 1));

            uint64_t dAh = make_desc(bufb);
            uint64_t dAl = make_desc(bufb + 16384);
            uint64_t dWh = make_desc(bufb + 32768);
            uint64_t dWl = make_desc(bufb + 49152);
#pragma unroll
            for (int s = 0; s < 4; s++) {
                uint64_t off = s * 2;
                mma_f16_ss(D, dAh + off, dWh + off, IDESC_128x128, !(n == 0 && s == 0));
                mma_f16_ss(D, dAh + off, dWl + off, IDESC_128x128, true);
                mma_f16_ss(D, dAl + off, dWh + off, IDESC_128x128, true);
            }
            TC_COMMIT(eb);
        }
        // driver drain (floor established by in-loop waits), then release all
        uint32_t pf = (uint32_t)(((NC >> 1) - 1) & 1);
        mbar_wait_parity(empty0, pf);
        mbar_wait_parity(empty1, pf);
        MBAR_ARRIVE(donem);
    }
    mbar_wait_parity(donem, 0u);
    TC_FENCE_AFTER();

    const int wg  = wid >> 2;
    const int sub = wid & 3;
    const int lr  = sub * 32 + lid;
    const int m   = m0 + lr;
    const int nkc_out = N >> 6;

#pragma unroll
    for (int bb = 0; bb < 2; bb++) {
        const int colbase = wg * 64 + bb * 32;
        uint32_t dr[32];
        LDTM32(dr, D + colbase);
        TC_WAIT_LD();
        float v[32];
#pragma unroll
        for (int c = 0; c < 32; c++) {
            float x = __uint_as_float(dr[c]) + __ldg(&bias[n0 + colbase + c]);
            v[c] = (x >= 0.f) ? x : SLOPE * x;
        }
        if (write_fp32) {
#pragma unroll
            for (int c = 0; c < 32; c++)
                Cfp[(size_t)m * N + n0 + colbase + c] = v[c];
        }
        if (write_split) {
#pragma unroll
            for (int g8 = 0; g8 < 4; g8++) {
                int nn = n0 + colbase + g8 * 8;
                int kc = nn >> 6, g = (nn & 63) >> 3;
                int gsw = g ^ (lr & 7);
                size_t off = (((size_t)mb * nkc_out + kc) * 128 + lr) * 64 + gsw * 8;
                bf16x8 ph, pl;
#pragma unroll
                for (int e = 0; e < 8; e++) {
                    float x = v[g8 * 8 + e];
                    __nv_bfloat16 h = __float2bfloat16(x);
                    ph.v[e] = h;
                    pl.v[e] = __float2bfloat16(x - __bfloat162float(h));
                }
                *(bf16x8*)&oh[off] = ph;
                *(bf16x8*)&ol[off] = pl;
            }
        }
    }

    __syncthreads();
    if (t == 0) {
        MBAR_INVAL(full0);  MBAR_INVAL(full1);
        MBAR_INVAL(empty0); MBAR_INVAL(empty1);
        MBAR_INVAL(donem);
    }
    __syncthreads();
    if (wid == 0) TC_DEALLOC(D, 128);

#else
    const int K = NC * 64;
    const int lr0 = t & 127;
    const int m = m0 + lr0;
    const int jh = (t >> 7) * 64;
    const int nkc_out = N >> 6;
    for (int jj = 0; jj < 64; jj++) {
        int nn = n0 + jh + jj;
        int wrb = nn >> 7, wlr = nn & 127;
        float acc = 0.f;
        for (int k = 0; k < K; k++) {
            int kc = k >> 6, g = (k & 63) >> 3, e = k & 7;
            size_t aoff = (((size_t)mb * NC + kc) * 128 + lr0) * 64 + (size_t)((g ^ (lr0 & 7)) * 8 + e);
            size_t woff = (((size_t)wrb * NC + kc) * 128 + wlr) * 64 + (size_t)((g ^ (wlr & 7)) * 8 + e);
            float av = __bfloat162float(ah[aoff]) + __bfloat162float(al[aoff]);
            float wv = __bfloat162float(wh[woff]) + __bfloat162float(wl[woff]);
            acc += av * wv;
        }
        float x = acc + bias[nn];
        x = (x >= 0.f) ? x : SLOPE * x;
        if (write_fp32) Cfp[(size_t)m * N + nn] = x;
        if (write_split) {
            __nv_bfloat16 h = __float2bfloat16(x);
            int kc = nn >> 6, g = (nn & 63) >> 3;
            size_t off = (((size_t)mb * nkc_out + kc) * 128 + lr0) * 64 + (size_t)((g ^ (lr0 & 7)) * 8 + (nn & 7));
            oh[off] = h;
            ol[off] = __float2bfloat16(x - __bfloat162float(h));
        }
    }
#endif
}

// ================= fused Gram + distance + stats, async-bulk pipeline =================
__global__ void __launch_bounds__(256, 2)
dist_stats_tc_kernel(const __nv_bfloat16* __restrict__ xh,
                     const __nv_bfloat16* __restrict__ xl,
                     const __nv_bfloat16* __restrict__ lh,
                     const __nv_bfloat16* __restrict__ ll,
                     const float* __restrict__ rx,
                     const float* __restrict__ rl) {
    int b = blockIdx.x;
    int bi = 0, rem = b;
    while (rem >= NB - bi) { rem -= NB - bi; bi++; }
    int bj = bi + rem;
    const bool diag = (bi == bj);
    const int i0 = bi * 128, j0 = bj * 128;

    __shared__ double red[256];
    const int t = threadIdx.x;

    float fs1 = 0.f, fs2 = 0.f, fs11 = 0.f, fs22 = 0.f, fs12 = 0.f;

#if HAS_TCGEN05
    extern __shared__ char dsm_raw[];
    char* dsm = (char*)(((uintptr_t)dsm_raw + 1023) & ~(uintptr_t)1023);
    __shared__ __align__(8) unsigned long long s_mbar[5];
    __shared__ uint32_t s_tmem;

    const int wid = t >> 5;
    const int lid = t & 31;
    const uint32_t full0  = smem_u32(&s_mbar[0]);
    const uint32_t full1  = full0 + 8;
    const uint32_t empty0 = full0 + 16;
    const uint32_t empty1 = full0 + 24;
    const uint32_t donem  = full0 + 32;

    if (wid == 0) TC_ALLOC(smem_u32(&s_tmem), 256);
    if (t == 0) {
        MBAR_INIT(full0, 1);  MBAR_INIT(full1, 1);
        MBAR_INIT(empty0, 1); MBAR_INIT(empty1, 1);
        MBAR_INIT(donem, 1);
    }
    __syncthreads();
    const uint32_t tmem = s_tmem;
    const uint32_t D_X = tmem, D_L = tmem + 128;
    const uint32_t smem_base = smem_u32(dsm);

    if (wid == 0 && elect_one()) {
        // chunks: 0..3 latent (hi->buf0 even, lo->buf1 odd; 12 MMAs at odd
        // chunks, double-committed to both empties), 4..19 x hi-only (4 MMAs).
        // Wait schedule (derived; consecutive indices per barrier):
        //   empty[n&1] parity ((n-2)>>1)&1 at chunk n>=2
        //   full[n&1]  parity (n>>1)&1     at every chunk
#pragma unroll 1
        for (int n = 0; n < NCH_DIST; n++) {
            const int bsel = n & 1;
            const uint32_t fb = bsel ? full1 : full0;
            const uint32_t eb = bsel ? empty1 : empty0;
            if (n >= 2) mbar_wait_parity(eb, (uint32_t)(((n - 2) >> 1) & 1));

            const __nv_bfloat16 *srcA, *srcB;
            if (n < 4) {
                int kc = n >> 1;
                const __nv_bfloat16* s = (n & 1) ? ll : lh;
                srcA = s + ((size_t)bi * NKC_L + kc) * TILE_ELEMS;
                srcB = s + ((size_t)bj * NKC_L + kc) * TILE_ELEMS;
            } else {
                int kc = n - 4;
                srcA = xh + ((size_t)bi * NKC_X + kc) * TILE_ELEMS;
                srcB = xh + ((size_t)bj * NKC_X + kc) * TILE_ELEMS;
            }
            const uint32_t bufb = smem_base + (uint32_t)bsel * 32768;
            MBAR_EXPECT_TX(fb, 32768);
            BULK_G2S(bufb,         (const char*)srcA, TILE_BYTES, fb);
            BULK_G2S(bufb + 16384, (const char*)srcB, TILE_BYTES, fb);
            mbar_wait_parity(fb, (uint32_t)((n >> 1) & 1));

            if (n >= 4) {
                uint64_t dA = make_desc(bufb), dB = make_desc(bufb + 16384);
#pragma unroll
                for (int s = 0; s < 4; s++)
                    mma_f16_ss(D_X, dA + s * 2, dB + s * 2, IDESC_128x128, !(n == 4 && s == 0));
                TC_COMMIT(eb);
            } else if (n & 1) {
                uint32_t b0 = smem_base, b1 = smem_base + 32768;
                uint64_t dAh = make_desc(b0), dBh = make_desc(b0 + 16384);
                uint64_t dAl = make_desc(b1), dBl = make_desc(b1 + 16384);
#pragma unroll
                for (int s = 0; s < 4; s++) {
                    uint64_t off = s * 2;
                    mma_f16_ss(D_L, dAh + off, dBh + off, IDESC_128x128, !(n == 1 && s == 0));
                    mma_f16_ss(D_L, dAh + off, dBl + off, IDESC_128x128, true);
                    mma_f16_ss(D_L, dAl + off, dBh + off, IDESC_128x128, true);
                }
                TC_COMMIT(empty0);
                TC_COMMIT(empty1);
            }
        }
        // drain: both empties have 10 commits; final idx 9 -> parity 1.
        mbar_wait_parity(empty0, 1u);
        mbar_wait_parity(empty1, 1u);
        MBAR_ARRIVE(donem);
    }
    mbar_wait_parity(donem, 0u);
    TC_FENCE_AFTER();

    const int wg  = wid >> 2;
    const int sub = wid & 3;
    const int i = i0 + sub * 32 + lid;
    const float rxi = __ldg(&rx[i]);
    const float rli = __ldg(&rl[i]);

#pragma unroll
    for (int bb = 0; bb < 2; bb++) {
        const int colbase = wg * 64 + bb * 32;
        uint32_t xg[32], lg[32];
        LDTM32(xg, D_X + colbase);
        LDTM32(lg, D_L + colbase);
        TC_WAIT_LD();
#pragma unroll
        for (int c = 0; c < 32; c++) {
            int j = j0 + colbase + c;
            if (!diag || j > i) {
                float gx = __uint_as_float(xg[c]);
                float gl = __uint_as_float(lg[c]);
                float sqx = rxi + __ldg(&rx[j]) - 2.f * gx;
                float sql = rli + __ldg(&rl[j]) - 2.f * gl;
                float dx = sqrtf(fmaxf(sqx, 0.f));
                float dv = sqrtf(fmaxf(sql, 0.f));
                fs1  += dx;
                fs2  += dv;
                fs11 += dx * dx;
                fs22 += dv * dv;
                fs12 += dx * dv;
            }
        }
    }

    __syncthreads();
    if (t == 0) {
        MBAR_INVAL(full0);  MBAR_INVAL(full1);
        MBAR_INVAL(empty0); MBAR_INVAL(empty1);
        MBAR_INVAL(donem);
    }
    __syncthreads();
    if (wid == 0) TC_DEALLOC(tmem, 256);

#else  // fallback: dequant fp32 (correct; never the selected cubin on GB300)
    const int tx8  = (t & 15) * 8;
    const int ty8  = (t >> 4) * 8;
    for (int ii = 0; ii < 8; ii++) {
        int i = i0 + ty8 + ii;
        float rxi = rx[i], rli = rl[i];
        int ib = i >> 7, ilr = i & 127;
        for (int jj = 0; jj < 8; jj++) {
            int j = j0 + tx8 + jj;
            if (diag && j <= i) continue;
            int jb = j >> 7, jlr = j & 127;
            float gx = 0.f, gl = 0.f;
            for (int k = 0; k < DIM; k++) {
                int kc = k >> 6, g = (k & 63) >> 3, e = k & 7;
                size_t ioff = (((size_t)ib * NKC_X + kc) * 128 + ilr) * 64 + (size_t)((g ^ (ilr & 7)) * 8 + e);
                size_t joff = (((size_t)jb * NKC_X + kc) * 128 + jlr) * 64 + (size_t)((g ^ (jlr & 7)) * 8 + e);
                gx += (__bfloat162float(xh[ioff]) + __bfloat162float(xl[ioff]))
                    * (__bfloat162float(xh[joff]) + __bfloat162float(xl[joff]));
            }
            for (int k = 0; k < LAT; k++) {
                int kc = k >> 6, g = (k & 63) >> 3, e = k & 7;
                size_t ioff = (((size_t)ib * NKC_L + kc) * 128 + ilr) * 64 + (size_t)((g ^ (ilr & 7)) * 8 + e);
                size_t joff = (((size_t)jb * NKC_L + kc) * 128 + jlr) * 64 + (size_t)((g ^ (jlr & 7)) * 8 + e);
                gl += (__bfloat162float(lh[ioff]) + __bfloat162float(ll[ioff]))
                    * (__bfloat162float(lh[joff]) + __bfloat162float(ll[joff]));
            }
            float dx = sqrtf(fmaxf(rxi + rx[j] - 2.f * gx, 0.f));
            float dv = sqrtf(fmaxf(rli + rl[j] - 2.f * gl, 0.f));
            fs1 += dx; fs2 += dv; fs11 += dx * dx; fs22 += dv * dv; fs12 += dx * dv;
        }
    }
#endif

    float vals[5] = {fs1, fs2, fs11, fs22, fs12};
#pragma unroll
    for (int v = 0; v < 5; v++) {
        red[t] = (double)vals[v];
        __syncthreads();
        for (int off = 128; off > 0; off >>= 1) {
            if (t < off) red[t] += red[t + off];
            __syncthreads();
        }
        if (t == 0) atomicAdd(&g_stats[v], red[0]);
        __syncthreads();
    }
}

__global__ void finalize_kernel(float* __restrict__ out, long long idx) {
    const double n = (double)N_ROWS * (double)N_ROWS;
    double s1  = 2.0 * g_stats[0];
    double s2  = 2.0 * g_stats[1];
    double s11 = 2.0 * g_stats[2];
    double s22 = 2.0 * g_stats[3];
    double s12 = 2.0 * g_stats[4];
    double m1 = s1 / n;
    double m2 = s2 / n;
    double v1 = (s11 - n * m1 * m1) / (n - 1.0);
    double v2 = (s22 - n * m2 * m2) / (n - 1.0);
    double cov = s12 / n - m1 * m2;
    out[idx] = (float)(cov / sqrt(v1 * v2));
}

extern "C" void kernel_launch(void* const* d_in, const int* in_sizes, int n_in,
                              void* d_out, int out_size) {
    const float* x   = (const float*)d_in[0];
    const float* We1 = (const float*)d_in[1];
    const float* be1 = (const float*)d_in[2];
    const float* We2 = (const float*)d_in[3];
    const float* be2 = (const float*)d_in[4];
    const float* We3 = (const float*)d_in[5];
    const float* be3 = (const float*)d_in[6];
    const float* Wd1 = (const float*)d_in[7];
    const float* bd1 = (const float*)d_in[8];
    const float* Wd2 = (const float*)d_in[9];
    const float* bd2 = (const float*)d_in[10];
    const float* Wd3 = (const float*)d_in[11];
    const float* bd3 = (const float*)d_in[12];
    float* out = (float*)d_out;

    float* lat = nullptr; cudaGetSymbolAddress((void**)&lat, g_lat);
    float* rx  = nullptr; cudaGetSymbolAddress((void**)&rx,  g_rx);
    float* rl  = nullptr; cudaGetSymbolAddress((void**)&rl,  g_rl);
#define SYM(T, v, s) T* v = nullptr; cudaGetSymbolAddress((void**)&v, s)
    SYM(__nv_bfloat16, xh, g_xh);   SYM(__nv_bfloat16, xl, g_xl);
    SYM(__nv_bfloat16, lh, g_lh);   SYM(__nv_bfloat16, ll, g_ll);
    SYM(__nv_bfloat16, a1h, g_a1h); SYM(__nv_bfloat16, a1l, g_a1l);
    SYM(__nv_bfloat16, a2h, g_a2h); SYM(__nv_bfloat16, a2l, g_a2l);
    SYM(__nv_bfloat16, a4h, g_a4h); SYM(__nv_bfloat16, a4l, g_a4l);
    SYM(__nv_bfloat16, a5h, g_a5h); SYM(__nv_bfloat16, a5l, g_a5l);
    SYM(__nv_bfloat16, we1h, g_we1h); SYM(__nv_bfloat16, we1l, g_we1l);
    SYM(__nv_bfloat16, we2h, g_we2h); SYM(__nv_bfloat16, we2l, g_we2l);
    SYM(__nv_bfloat16, we3h, g_we3h); SYM(__nv_bfloat16, we3l, g_we3l);
    SYM(__nv_bfloat16, wd1h, g_wd1h); SYM(__nv_bfloat16, wd1l, g_wd1l);
    SYM(__nv_bfloat16, wd2h, g_wd2h); SYM(__nv_bfloat16, wd2l, g_wd2l);
    SYM(__nv_bfloat16, wd3h, g_wd3h); SYM(__nv_bfloat16, wd3l, g_wd3l);
#undef SYM

    zero_stats_kernel<<<1, 32>>>();

    {
        CvtArgs a;
        unsigned base = 0;
        auto set = [&](int i, const float* src, __nv_bfloat16* dh, __nv_bfloat16* dl,
                       int rows, int K) {
            a.seg[i] = {src, dh, dl, K, base};
            base += (unsigned)(rows * K / 8);
        };
        set(0, x,   xh,   xl,   N_ROWS, DIM);
        set(1, We1, we1h, we1l, H1,  DIM);
        set(2, We2, we2h, we2l, H2,  H1);
        set(3, We3, we3h, we3l, LAT, H2);
        set(4, Wd1, wd1h, wd1l, H2,  LAT);
        set(5, Wd2, wd2h, wd2l, H1,  H2);
        set(6, Wd3, wd3h, wd3l, DIM, H1);
        a.total = base;
        convert_all_kernel<<<(base + 255) / 256, 256>>>(a);
    }
    rownorm_kernel<<<N_ROWS, 256>>>(x, rx, DIM);

    const int smem_gemm = 2 * 65536 + 1024;
    const int smem_dist = 2 * 32768 + 1024;
    cudaFuncSetAttribute(tc_gemm_bias_lrelu, cudaFuncAttributeMaxDynamicSharedMemorySize, smem_gemm);
    cudaFuncSetAttribute(dist_stats_tc_kernel, cudaFuncAttributeMaxDynamicSharedMemorySize, smem_dist);

#define TCL(ah_, al_, wh_, wl_, b_, c_, oh_, ol_, N_, K_, wf, ws) \
    tc_gemm_bias_lrelu<<<dim3((N_) / 128, NB), 256, smem_gemm>>>( \
        ah_, al_, wh_, wl_, b_, c_, oh_, ol_, N_, (K_) / 64, wf, ws)
    TCL(xh,  xl,  we1h, we1l, be1, (float*)nullptr, a1h, a1l, H1,  DIM, 0, 1);
    TCL(a1h, a1l, we2h, we2l, be2, (float*)nullptr, a2h, a2l, H2,  H1,  0, 1);
    TCL(a2h, a2l, we3h, we3l, be3, lat,             lh,  ll,  LAT, H2,  1, 1);
    rownorm_kernel<<<N_ROWS, 128>>>(lat, rl, LAT);
    TCL(lh,  ll,  wd1h, wd1l, bd1, (float*)nullptr, a4h, a4l, H2,  LAT, 0, 1);
    TCL(a4h, a4l, wd2h, wd2l, bd2, (float*)nullptr, a5h, a5l, H1,  H2,  0, 1);
    TCL(a5h, a5l, wd3h, wd3l, bd3, out,  (__nv_bfloat16*)nullptr, (__nv_bfloat16*)nullptr, DIM, H1, 1, 0);
#undef TCL

    dist_stats_tc_kernel<<<NB * (NB + 1) / 2, 256, smem_dist>>>(xh, xl, lh, ll, rx, rl);

    finalize_kernel<<<1, 1>>>(out, (long long)out_size - 1);
}

// round 9
// speedup vs baseline: 6.0705x; 1.2227x over previous
#include <cuda_runtime.h>
#include <cuda_bf16.h>
#include <math.h>
#include <stdint.h>

#define N_ROWS 4096
#define DIM    1024
#define H1     512
#define H2     256
#define LAT    128
#define SLOPE  0.01f
#define NB     (N_ROWS / 128)
#define NKC_X  (DIM / 64)
#define NKC_L  (LAT / 64)
#define TILE_ELEMS 8192
#define TILE_BYTES 16384
#define NCH_DIST (NKC_L + NKC_X)    /* 18 uniform hi-only chunks */

#if defined(__CUDA_ARCH_FEAT_SM103_ALL) || defined(__CUDA_ARCH_FEAT_SM100_ALL) || defined(__CUDA_ARCH_FEAT_SM101_ALL)
#define HAS_TCGEN05 1
#else
#define HAS_TCGEN05 0
#endif

// -------- scratch --------
__device__ float g_lat[N_ROWS * LAT];
__device__ float g_rx[N_ROWS];
__device__ float g_rl[N_ROWS];
__device__ double g_stats[5];
__device__ __align__(16) __nv_bfloat16 g_xh[NB * NKC_X * TILE_ELEMS];
__device__ __align__(16) __nv_bfloat16 g_xl[NB * NKC_X * TILE_ELEMS];
__device__ __align__(16) __nv_bfloat16 g_lh[NB * NKC_L * TILE_ELEMS];
__device__ __align__(16) __nv_bfloat16 g_ll[NB * NKC_L * TILE_ELEMS];
__device__ __align__(16) __nv_bfloat16 g_a1h[N_ROWS * H1], g_a1l[N_ROWS * H1];
__device__ __align__(16) __nv_bfloat16 g_a2h[N_ROWS * H2], g_a2l[N_ROWS * H2];
__device__ __align__(16) __nv_bfloat16 g_a4h[N_ROWS * H2], g_a4l[N_ROWS * H2];
__device__ __align__(16) __nv_bfloat16 g_a5h[N_ROWS * H1], g_a5l[N_ROWS * H1];
__device__ __align__(16) __nv_bfloat16 g_we1h[H1 * DIM], g_we1l[H1 * DIM];
__device__ __align__(16) __nv_bfloat16 g_we2h[H2 * H1],  g_we2l[H2 * H1];
__device__ __align__(16) __nv_bfloat16 g_we3h[LAT * H2], g_we3l[LAT * H2];
__device__ __align__(16) __nv_bfloat16 g_wd1h[H2 * LAT], g_wd1l[H2 * LAT];
__device__ __align__(16) __nv_bfloat16 g_wd2h[H1 * H2],  g_wd2l[H1 * H2];
__device__ __align__(16) __nv_bfloat16 g_wd3h[DIM * H1], g_wd3l[DIM * H1];

__global__ void zero_stats_kernel() {
    if (threadIdx.x < 5) g_stats[threadIdx.x] = 0.0;
}

// ================= PTX helpers =================
__device__ __forceinline__ uint32_t smem_u32(const void* p) {
    uint32_t a;
    asm("{ .reg .u64 t; cvta.to.shared.u64 t, %1; cvt.u32.u64 %0, t; }" : "=r"(a) : "l"(p));
    return a;
}
__device__ __forceinline__ uint32_t elect_one() {
    uint32_t p;
    asm volatile("{\n\t.reg .pred p;\n\telect.sync _|p, 0xFFFFFFFF;\n\tselp.b32 %0, 1, 0, p;\n\t}" : "=r"(p));
    return p;
}
#define MBAR_INIT(mbar, c) \
    asm volatile("mbarrier.init.shared.b64 [%0], %1;" :: "r"(mbar), "r"((uint32_t)(c)) : "memory")
#define MBAR_INVAL(mbar) \
    asm volatile("mbarrier.inval.shared.b64 [%0];" :: "r"(mbar) : "memory")
#define MBAR_ARRIVE(mbar) \
    asm volatile("mbarrier.arrive.shared.b64 _, [%0];" :: "r"(mbar) : "memory")
#define MBAR_EXPECT_TX(mbar, bytes) \
    asm volatile("mbarrier.arrive.expect_tx.shared.b64 _, [%0], %1;" \
                 :: "r"(mbar), "r"((uint32_t)(bytes)) : "memory")

__device__ __forceinline__ void mbar_wait_parity(uint32_t mbar, uint32_t parity) {
    uint32_t done;
    asm volatile("{\n\t.reg .pred p;\n\t"
                 "mbarrier.try_wait.parity.acquire.cta.shared::cta.b64 p, [%1], %2;\n\t"
                 "selp.b32 %0, 1, 0, p;\n\t}" : "=r"(done) : "r"(mbar), "r"(parity) : "memory");
    if (!done) {
        asm volatile("{\n\t.reg .pred P1;\n\t"
                     "WL_%=:\n\t"
                     "mbarrier.try_wait.parity.acquire.cta.shared::cta.b64 P1, [%0], %1, 0x989680;\n\t"
                     "@P1 bra.uni WD_%=;\n\t"
                     "bra.uni WL_%=;\n\t"
                     "WD_%=:\n\t}" :: "r"(mbar), "r"(parity) : "memory");
    }
}

#if HAS_TCGEN05
#define TC_ALLOC(smem_addr, n) \
    asm volatile("tcgen05.alloc.cta_group::1.sync.aligned.shared::cta.b32 [%0], %1;" \
                 :: "r"(smem_addr), "r"((uint32_t)(n)) : "memory")
#define TC_DEALLOC(tmem, n) \
    asm volatile("tcgen05.dealloc.cta_group::1.sync.aligned.b32 %0, %1;" :: "r"(tmem), "r"((uint32_t)(n)))
#define TC_COMMIT(mbar) \
    asm volatile("tcgen05.commit.cta_group::1.mbarrier::arrive::one.shared::cluster.b64 [%0];" \
                 :: "r"(mbar) : "memory")
#define TC_FENCE_AFTER()  asm volatile("tcgen05.fence::after_thread_sync;" ::: "memory")
#define TC_WAIT_LD()      asm volatile("tcgen05.wait::ld.sync.aligned;" ::: "memory")
#define BULK_G2S(dst, src, bytes, mbar) \
    asm volatile("cp.async.bulk.shared::cta.global.mbarrier::complete_tx::bytes [%0], [%1], %2, [%3];" \
                 :: "r"(dst), "l"(src), "r"((uint32_t)(bytes)), "r"(mbar) : "memory")

__device__ __forceinline__ void mma_f16_ss(uint32_t d_tmem, uint64_t a_desc, uint64_t b_desc,
                                           uint32_t idesc, bool accum) {
    uint32_t en = accum ? 1u : 0u;
    asm volatile("{\n\t.reg .pred p;\n\t"
                 "setp.ne.u32 p, %5, 0;\n\t"
                 "tcgen05.mma.cta_group::1.kind::f16 [%0], %1, %2, %3, {%4, %4, %4, %4}, p;\n\t}"
                 :: "r"(d_tmem), "l"(a_desc), "l"(b_desc), "r"(idesc), "r"(0u), "r"(en)
                 : "memory");
}

#define LDTM32(r, addr) \
    asm volatile("tcgen05.ld.sync.aligned.32x32b.x32.b32 " \
        "{%0, %1, %2, %3, %4, %5, %6, %7, %8, %9, %10, %11, %12, %13, %14, %15, " \
        " %16, %17, %18, %19, %20, %21, %22, %23, %24, %25, %26, %27, %28, %29, %30, %31}, [%32];" \
        : "=r"((r)[0]), "=r"((r)[1]), "=r"((r)[2]), "=r"((r)[3]), \
          "=r"((r)[4]), "=r"((r)[5]), "=r"((r)[6]), "=r"((r)[7]), \
          "=r"((r)[8]), "=r"((r)[9]), "=r"((r)[10]), "=r"((r)[11]), \
          "=r"((r)[12]), "=r"((r)[13]), "=r"((r)[14]), "=r"((r)[15]), \
          "=r"((r)[16]), "=r"((r)[17]), "=r"((r)[18]), "=r"((r)[19]), \
          "=r"((r)[20]), "=r"((r)[21]), "=r"((r)[22]), "=r"((r)[23]), \
          "=r"((r)[24]), "=r"((r)[25]), "=r"((r)[26]), "=r"((r)[27]), \
          "=r"((r)[28]), "=r"((r)[29]), "=r"((r)[30]), "=r"((r)[31]) \
        : "r"(addr))

static __device__ __forceinline__ uint64_t make_desc(uint32_t addr) {
    const uint64_t base = (uint64_t(2) << 61) | (uint64_t(1) << 46)
                        | (uint64_t(64) << 32) | (uint64_t(1) << 16);
    return base | ((uint64_t)(addr >> 4) & 0x3FFF);
}
#define IDESC_128x128 0x8200490u
#endif // HAS_TCGEN05

// ================= row squared-norms =================
__global__ void rownorm_kernel(const float* __restrict__ X, float* __restrict__ r, int K) {
    int row = blockIdx.x;
    const float* p = X + (size_t)row * K;
    float s = 0.f;
    for (int k = threadIdx.x; k < K; k += blockDim.x) {
        float v = p[k];
        s += v * v;
    }
#pragma unroll
    for (int off = 16; off > 0; off >>= 1)
        s += __shfl_down_sync(0xffffffffu, s, off);
    __shared__ float sm[32];
    int lane = threadIdx.x & 31, wid = threadIdx.x >> 5;
    if (lane == 0) sm[wid] = s;
    __syncthreads();
    if (wid == 0) {
        int nw = blockDim.x >> 5;
        float v = (lane < nw) ? sm[lane] : 0.f;
#pragma unroll
        for (int off = 16; off > 0; off >>= 1)
            v += __shfl_down_sync(0xffffffffu, v, off);
        if (lane == 0) r[row] = v;
    }
}

// ================= fused split-convert =================
struct alignas(16) bf16x8 { __nv_bfloat16 v[8]; };
struct CvtSeg { const float* src; __nv_bfloat16* dh; __nv_bfloat16* dl; int K; unsigned base; };
struct CvtArgs { CvtSeg seg[7]; unsigned total; };

__global__ void convert_all_kernel(CvtArgs args) {
    unsigned gid = blockIdx.x * blockDim.x + threadIdx.x;
    if (gid >= args.total) return;
    int si = 0;
#pragma unroll
    for (int i = 1; i < 7; i++)
        if (gid >= args.seg[i].base) si = i;
    const CvtSeg s = args.seg[si];
    unsigned idx = gid - s.base;
    int K = s.K, gpr = K >> 3, nkc = K >> 6;
    int r  = idx / gpr;
    int k0 = (idx - r * gpr) * 8;

    const float* p = s.src + (size_t)r * K + k0;
    float4 v0 = *(const float4*)p;
    float4 v1 = *(const float4*)(p + 4);
    float f[8] = {v0.x, v0.y, v0.z, v0.w, v1.x, v1.y, v1.z, v1.w};

    bf16x8 ph, pl;
#pragma unroll
    for (int m = 0; m < 8; m++) {
        __nv_bfloat16 h = __float2bfloat16(f[m]);
        ph.v[m] = h;
        pl.v[m] = __float2bfloat16(f[m] - __bfloat162float(h));
    }

    int rb = r >> 7, lr = r & 127;
    int kc = k0 >> 6, g = (k0 & 63) >> 3;
    int gsw = g ^ (lr & 7);
    size_t off = (((size_t)rb * nkc + kc) * 128 + lr) * 64 + gsw * 8;
    *(bf16x8*)&s.dh[off] = ph;
    *(bf16x8*)&s.dl[off] = pl;
}

// ================= tcgen05 GEMM + bias + LeakyReLU, depth-3 pipeline =================
// Driver order per chunk n: wait full(n) -> MMA(n) -> commit empty(n) ->
// wait empty(n) [fires on MMA-n completion] -> copy chunk n+S into same buffer.
// Every barrier is waited at consecutive indices by the single driver, so at
// most one phase is pending at each wait (parity-safe). Copies run S-1 deep.
#define GS 3
__global__ void __launch_bounds__(256, 1)
tc_gemm_bias_lrelu(const __nv_bfloat16* __restrict__ ah, const __nv_bfloat16* __restrict__ al,
                   const __nv_bfloat16* __restrict__ wh, const __nv_bfloat16* __restrict__ wl,
                   const float* __restrict__ bias,
                   float* __restrict__ Cfp,
                   __nv_bfloat16* __restrict__ oh, __nv_bfloat16* __restrict__ ol,
                   int N, int NC, int write_fp32, int write_split) {
    const int nb = blockIdx.x, mb = blockIdx.y;
    const int n0 = nb * 128, m0 = mb * 128;
    const int t = threadIdx.x;

#if HAS_TCGEN05
    extern __shared__ char dsm_raw[];
    char* dsm = (char*)(((uintptr_t)dsm_raw + 1023) & ~(uintptr_t)1023);
    __shared__ __align__(8) unsigned long long s_mbar[2 * GS + 1];
    __shared__ uint32_t s_tmem;

    const int wid = t >> 5;
    const int lid = t & 31;
    const uint32_t mb0   = smem_u32(&s_mbar[0]);
    const uint32_t donem = mb0 + 2 * GS * 8;
#define FULLB(b)  (mb0 + (uint32_t)(b) * 8)
#define EMPTYB(b) (mb0 + (uint32_t)(GS + (b)) * 8)

    if (wid == 0) TC_ALLOC(smem_u32(&s_tmem), 128);
    if (t == 0) {
        for (int k = 0; k < 2 * GS; k++) MBAR_INIT(mb0 + k * 8, 1);
        MBAR_INIT(donem, 1);
    }
    __syncthreads();
    const uint32_t D = s_tmem;
    const uint32_t smem_base = smem_u32(dsm);

    if (wid == 0 && elect_one()) {
        const int np = (NC < GS) ? NC : GS;
        // prologue: fill all stage buffers
        for (int k = 0; k < np; k++) {
            const uint32_t bufb = smem_base + (uint32_t)k * 65536;
            MBAR_EXPECT_TX(FULLB(k), 65536);
            BULK_G2S(bufb,         (const char*)(ah + ((size_t)mb * NC + k) * TILE_ELEMS), TILE_BYTES, FULLB(k));
            BULK_G2S(bufb + 16384, (const char*)(al + ((size_t)mb * NC + k) * TILE_ELEMS), TILE_BYTES, FULLB(k));
            BULK_G2S(bufb + 32768, (const char*)(wh + ((size_t)nb * NC + k) * TILE_ELEMS), TILE_BYTES, FULLB(k));
            BULK_G2S(bufb + 49152, (const char*)(wl + ((size_t)nb * NC + k) * TILE_ELEMS), TILE_BYTES, FULLB(k));
        }
#pragma unroll 1
        for (int n = 0; n < NC; n++) {
            const int b = n % GS, q = n / GS;
            const uint32_t bufb = smem_base + (uint32_t)b * 65536;
            mbar_wait_parity(FULLB(b), (uint32_t)(q & 1));

            uint64_t dAh = make_desc(bufb);
            uint64_t dAl = make_desc(bufb + 16384);
            uint64_t dWh = make_desc(bufb + 32768);
            uint64_t dWl = make_desc(bufb + 49152);
#pragma unroll
            for (int s = 0; s < 4; s++) {
                uint64_t off = s * 2;
                mma_f16_ss(D, dAh + off, dWh + off, IDESC_128x128, !(n == 0 && s == 0));
                mma_f16_ss(D, dAh + off, dWl + off, IDESC_128x128, true);
                mma_f16_ss(D, dAl + off, dWh + off, IDESC_128x128, true);
            }
            TC_COMMIT(EMPTYB(b));

            if (n + GS < NC) {
                const int m = n + GS;
                mbar_wait_parity(EMPTYB(b), (uint32_t)(q & 1));
                MBAR_EXPECT_TX(FULLB(b), 65536);
                BULK_G2S(bufb,         (const char*)(ah + ((size_t)mb * NC + m) * TILE_ELEMS), TILE_BYTES, FULLB(b));
                BULK_G2S(bufb + 16384, (const char*)(al + ((size_t)mb * NC + m) * TILE_ELEMS), TILE_BYTES, FULLB(b));
                BULK_G2S(bufb + 32768, (const char*)(wh + ((size_t)nb * NC + m) * TILE_ELEMS), TILE_BYTES, FULLB(b));
                BULK_G2S(bufb + 49152, (const char*)(wl + ((size_t)nb * NC + m) * TILE_ELEMS), TILE_BYTES, FULLB(b));
            }
        }
        // drain the last min(GS,NC) commits (sequential per buffer)
        for (int n = (NC > GS ? NC - GS : 0); n < NC; n++)
            mbar_wait_parity(EMPTYB(n % GS), (uint32_t)((n / GS) & 1));
        MBAR_ARRIVE(donem);
    }
    mbar_wait_parity(donem, 0u);
    TC_FENCE_AFTER();

    const int wg  = wid >> 2;
    const int sub = wid & 3;
    const int lr  = sub * 32 + lid;
    const int m   = m0 + lr;
    const int nkc_out = N >> 6;

#pragma unroll
    for (int bb = 0; bb < 2; bb++) {
        const int colbase = wg * 64 + bb * 32;
        uint32_t dr[32];
        LDTM32(dr, D + colbase);
        TC_WAIT_LD();
        float v[32];
#pragma unroll
        for (int c = 0; c < 32; c++) {
            float x = __uint_as_float(dr[c]) + __ldg(&bias[n0 + colbase + c]);
            v[c] = (x >= 0.f) ? x : SLOPE * x;
        }
        if (write_fp32) {
#pragma unroll
            for (int c = 0; c < 32; c++)
                Cfp[(size_t)m * N + n0 + colbase + c] = v[c];
        }
        if (write_split) {
#pragma unroll
            for (int g8 = 0; g8 < 4; g8++) {
                int nn = n0 + colbase + g8 * 8;
                int kc = nn >> 6, g = (nn & 63) >> 3;
                int gsw = g ^ (lr & 7);
                size_t off = (((size_t)mb * nkc_out + kc) * 128 + lr) * 64 + gsw * 8;
                bf16x8 ph, pl;
#pragma unroll
                for (int e = 0; e < 8; e++) {
                    float x = v[g8 * 8 + e];
                    __nv_bfloat16 h = __float2bfloat16(x);
                    ph.v[e] = h;
                    pl.v[e] = __float2bfloat16(x - __bfloat162float(h));
                }
                *(bf16x8*)&oh[off] = ph;
                *(bf16x8*)&ol[off] = pl;
            }
        }
    }

    __syncthreads();
    if (t == 0) {
        for (int k = 0; k < 2 * GS; k++) MBAR_INVAL(mb0 + k * 8);
        MBAR_INVAL(donem);
    }
    __syncthreads();
    if (wid == 0) TC_DEALLOC(D, 128);
#undef FULLB
#undef EMPTYB

#else
    const int K = NC * 64;
    const int lr0 = t & 127;
    const int m = m0 + lr0;
    const int jh = (t >> 7) * 64;
    const int nkc_out = N >> 6;
    for (int jj = 0; jj < 64; jj++) {
        int nn = n0 + jh + jj;
        int wrb = nn >> 7, wlr = nn & 127;
        float acc = 0.f;
        for (int k = 0; k < K; k++) {
            int kc = k >> 6, g = (k & 63) >> 3, e = k & 7;
            size_t aoff = (((size_t)mb * NC + kc) * 128 + lr0) * 64 + (size_t)((g ^ (lr0 & 7)) * 8 + e);
            size_t woff = (((size_t)wrb * NC + kc) * 128 + wlr) * 64 + (size_t)((g ^ (wlr & 7)) * 8 + e);
            float av = __bfloat162float(ah[aoff]) + __bfloat162float(al[aoff]);
            float wv = __bfloat162float(wh[woff]) + __bfloat162float(wl[woff]);
            acc += av * wv;
        }
        float x = acc + bias[nn];
        x = (x >= 0.f) ? x : SLOPE * x;
        if (write_fp32) Cfp[(size_t)m * N + nn] = x;
        if (write_split) {
            __nv_bfloat16 h = __float2bfloat16(x);
            int kc = nn >> 6, g = (nn & 63) >> 3;
            size_t off = (((size_t)mb * nkc_out + kc) * 128 + lr0) * 64 + (size_t)((g ^ (lr0 & 7)) * 8 + (nn & 7));
            oh[off] = h;
            ol[off] = __float2bfloat16(x - __bfloat162float(h));
        }
    }
#endif
}

// ================= fused Gram + distance + stats, uniform hi-only, depth-3 =================
#define DS 3
__global__ void __launch_bounds__(256, 2)
dist_stats_tc_kernel(const __nv_bfloat16* __restrict__ xh,
                     const __nv_bfloat16* __restrict__ lh,
                     const float* __restrict__ rx,
                     const float* __restrict__ rl) {
    int b = blockIdx.x;
    int bi = 0, rem = b;
    while (rem >= NB - bi) { rem -= NB - bi; bi++; }
    int bj = bi + rem;
    const bool diag = (bi == bj);
    const int i0 = bi * 128, j0 = bj * 128;

    __shared__ double red[256];
    const int t = threadIdx.x;

    float fs1 = 0.f, fs2 = 0.f, fs11 = 0.f, fs22 = 0.f, fs12 = 0.f;

#if HAS_TCGEN05
    extern __shared__ char dsm_raw[];
    char* dsm = (char*)(((uintptr_t)dsm_raw + 1023) & ~(uintptr_t)1023);
    __shared__ __align__(8) unsigned long long s_mbar[2 * DS + 1];
    __shared__ uint32_t s_tmem;

    const int wid = t >> 5;
    const int lid = t & 31;
    const uint32_t mb0   = smem_u32(&s_mbar[0]);
    const uint32_t donem = mb0 + 2 * DS * 8;
#define FULLB(b)  (mb0 + (uint32_t)(b) * 8)
#define EMPTYB(b) (mb0 + (uint32_t)(DS + (b)) * 8)

    if (wid == 0) TC_ALLOC(smem_u32(&s_tmem), 256);
    if (t == 0) {
        for (int k = 0; k < 2 * DS; k++) MBAR_INIT(mb0 + k * 8, 1);
        MBAR_INIT(donem, 1);
    }
    __syncthreads();
    const uint32_t tmem = s_tmem;
    const uint32_t D_X = tmem, D_L = tmem + 128;
    const uint32_t smem_base = smem_u32(dsm);

    if (wid == 0 && elect_one()) {
        // chunks 0..1: latent hi; 2..17: x hi. 4 MMAs each.
        auto srcs = [&](int n, const __nv_bfloat16*& sA, const __nv_bfloat16*& sB) {
            if (n < NKC_L) {
                sA = lh + ((size_t)bi * NKC_L + n) * TILE_ELEMS;
                sB = lh + ((size_t)bj * NKC_L + n) * TILE_ELEMS;
            } else {
                int kc = n - NKC_L;
                sA = xh + ((size_t)bi * NKC_X + kc) * TILE_ELEMS;
                sB = xh + ((size_t)bj * NKC_X + kc) * TILE_ELEMS;
            }
        };
        for (int k = 0; k < DS; k++) {
            const __nv_bfloat16 *sA, *sB;
            srcs(k, sA, sB);
            const uint32_t bufb = smem_base + (uint32_t)k * 32768;
            MBAR_EXPECT_TX(FULLB(k), 32768);
            BULK_G2S(bufb,         (const char*)sA, TILE_BYTES, FULLB(k));
            BULK_G2S(bufb + 16384, (const char*)sB, TILE_BYTES, FULLB(k));
        }
#pragma unroll 1
        for (int n = 0; n < NCH_DIST; n++) {
            const int bsel = n % DS, q = n / DS;
            const uint32_t bufb = smem_base + (uint32_t)bsel * 32768;
            mbar_wait_parity(FULLB(bsel), (uint32_t)(q & 1));

            const uint32_t Dacc = (n < NKC_L) ? D_L : D_X;
            const bool first = (n == 0) || (n == NKC_L);
            uint64_t dA = make_desc(bufb), dB = make_desc(bufb + 16384);
#pragma unroll
            for (int s = 0; s < 4; s++)
                mma_f16_ss(Dacc, dA + s * 2, dB + s * 2, IDESC_128x128, !(first && s == 0));
            TC_COMMIT(EMPTYB(bsel));

            if (n + DS < NCH_DIST) {
                const __nv_bfloat16 *sA, *sB;
                srcs(n + DS, sA, sB);
                mbar_wait_parity(EMPTYB(bsel), (uint32_t)(q & 1));
                MBAR_EXPECT_TX(FULLB(bsel), 32768);
                BULK_G2S(bufb,         (const char*)sA, TILE_BYTES, FULLB(bsel));
                BULK_G2S(bufb + 16384, (const char*)sB, TILE_BYTES, FULLB(bsel));
            }
        }
        for (int n = NCH_DIST - DS; n < NCH_DIST; n++)
            mbar_wait_parity(EMPTYB(n % DS), (uint32_t)((n / DS) & 1));
        MBAR_ARRIVE(donem);
    }
    mbar_wait_parity(donem, 0u);
    TC_FENCE_AFTER();

    const int wg  = wid >> 2;
    const int sub = wid & 3;
    const int i = i0 + sub * 32 + lid;
    const float rxi = __ldg(&rx[i]);
    const float rli = __ldg(&rl[i]);

#pragma unroll
    for (int bb = 0; bb < 2; bb++) {
        const int colbase = wg * 64 + bb * 32;
        uint32_t xg[32], lg[32];
        LDTM32(xg, D_X + colbase);
        LDTM32(lg, D_L + colbase);
        TC_WAIT_LD();
#pragma unroll
        for (int c = 0; c < 32; c++) {
            int j = j0 + colbase + c;
            if (!diag || j > i) {
                float gx = __uint_as_float(xg[c]);
                float gl = __uint_as_float(lg[c]);
                float sqx = rxi + __ldg(&rx[j]) - 2.f * gx;
                float sql = rli + __ldg(&rl[j]) - 2.f * gl;
                float dx = sqrtf(fmaxf(sqx, 0.f));
                float dv = sqrtf(fmaxf(sql, 0.f));
                fs1  += dx;
                fs2  += dv;
                fs11 += dx * dx;
                fs22 += dv * dv;
                fs12 += dx * dv;
            }
        }
    }

    __syncthreads();
    if (t == 0) {
        for (int k = 0; k < 2 * DS; k++) MBAR_INVAL(mb0 + k * 8);
        MBAR_INVAL(donem);
    }
    __syncthreads();
    if (wid == 0) TC_DEALLOC(tmem, 256);
#undef FULLB
#undef EMPTYB

#else  // fallback: dequant fp32 hi-only (correct; never the selected cubin on GB300)
    const int tx8  = (t & 15) * 8;
    const int ty8  = (t >> 4) * 8;
    for (int ii = 0; ii < 8; ii++) {
        int i = i0 + ty8 + ii;
        float rxi = rx[i], rli = rl[i];
        int ib = i >> 7, ilr = i & 127;
        for (int jj = 0; jj < 8; jj++) {
            int j = j0 + tx8 + jj;
            if (diag && j <= i) continue;
            int jb = j >> 7, jlr = j & 127;
            float gx = 0.f, gl = 0.f;
            for (int k = 0; k < DIM; k++) {
                int kc = k >> 6, g = (k & 63) >> 3, e = k & 7;
                size_t ioff = (((size_t)ib * NKC_X + kc) * 128 + ilr) * 64 + (size_t)((g ^ (ilr & 7)) * 8 + e);
                size_t joff = (((size_t)jb * NKC_X + kc) * 128 + jlr) * 64 + (size_t)((g ^ (jlr & 7)) * 8 + e);
                gx += __bfloat162float(xh[ioff]) * __bfloat162float(xh[joff]);
            }
            for (int k = 0; k < LAT; k++) {
                int kc = k >> 6, g = (k & 63) >> 3, e = k & 7;
                size_t ioff = (((size_t)ib * NKC_L + kc) * 128 + ilr) * 64 + (size_t)((g ^ (ilr & 7)) * 8 + e);
                size_t joff = (((size_t)jb * NKC_L + kc) * 128 + jlr) * 64 + (size_t)((g ^ (jlr & 7)) * 8 + e);
                gl += __bfloat162float(lh[ioff]) * __bfloat162float(lh[joff]);
            }
            float dx = sqrtf(fmaxf(rxi + rx[j] - 2.f * gx, 0.f));
            float dv = sqrtf(fmaxf(rli + rl[j] - 2.f * gl, 0.f));
            fs1 += dx; fs2 += dv; fs11 += dx * dx; fs22 += dv * dv; fs12 += dx * dv;
        }
    }
#endif

    float vals[5] = {fs1, fs2, fs11, fs22, fs12};
#pragma unroll
    for (int v = 0; v < 5; v++) {
        red[t] = (double)vals[v];
        __syncthreads();
        for (int off = 128; off > 0; off >>= 1) {
            if (t < off) red[t] += red[t + off];
            __syncthreads();
        }
        if (t == 0) atomicAdd(&g_stats[v], red[0]);
        __syncthreads();
    }
}

__global__ void finalize_kernel(float* __restrict__ out, long long idx) {
    const double n = (double)N_ROWS * (double)N_ROWS;
    double s1  = 2.0 * g_stats[0];
    double s2  = 2.0 * g_stats[1];
    double s11 = 2.0 * g_stats[2];
    double s22 = 2.0 * g_stats[3];
    double s12 = 2.0 * g_stats[4];
    double m1 = s1 / n;
    double m2 = s2 / n;
    double v1 = (s11 - n * m1 * m1) / (n - 1.0);
    double v2 = (s22 - n * m2 * m2) / (n - 1.0);
    double cov = s12 / n - m1 * m2;
    out[idx] = (float)(cov / sqrt(v1 * v2));
}

extern "C" void kernel_launch(void* const* d_in, const int* in_sizes, int n_in,
                              void* d_out, int out_size) {
    const float* x   = (const float*)d_in[0];
    const float* We1 = (const float*)d_in[1];
    const float* be1 = (const float*)d_in[2];
    const float* We2 = (const float*)d_in[3];
    const float* be2 = (const float*)d_in[4];
    const float* We3 = (const float*)d_in[5];
    const float* be3 = (const float*)d_in[6];
    const float* Wd1 = (const float*)d_in[7];
    const float* bd1 = (const float*)d_in[8];
    const float* Wd2 = (const float*)d_in[9];
    const float* bd2 = (const float*)d_in[10];
    const float* Wd3 = (const float*)d_in[11];
    const float* bd3 = (const float*)d_in[12];
    float* out = (float*)d_out;

    float* lat = nullptr; cudaGetSymbolAddress((void**)&lat, g_lat);
    float* rx  = nullptr; cudaGetSymbolAddress((void**)&rx,  g_rx);
    float* rl  = nullptr; cudaGetSymbolAddress((void**)&rl,  g_rl);
#define SYM(T, v, s) T* v = nullptr; cudaGetSymbolAddress((void**)&v, s)
    SYM(__nv_bfloat16, xh, g_xh);   SYM(__nv_bfloat16, xl, g_xl);
    SYM(__nv_bfloat16, lh, g_lh);   SYM(__nv_bfloat16, ll, g_ll);
    SYM(__nv_bfloat16, a1h, g_a1h); SYM(__nv_bfloat16, a1l, g_a1l);
    SYM(__nv_bfloat16, a2h, g_a2h); SYM(__nv_bfloat16, a2l, g_a2l);
    SYM(__nv_bfloat16, a4h, g_a4h); SYM(__nv_bfloat16, a4l, g_a4l);
    SYM(__nv_bfloat16, a5h, g_a5h); SYM(__nv_bfloat16, a5l, g_a5l);
    SYM(__nv_bfloat16, we1h, g_we1h); SYM(__nv_bfloat16, we1l, g_we1l);
    SYM(__nv_bfloat16, we2h, g_we2h); SYM(__nv_bfloat16, we2l, g_we2l);
    SYM(__nv_bfloat16, we3h, g_we3h); SYM(__nv_bfloat16, we3l, g_we3l);
    SYM(__nv_bfloat16, wd1h, g_wd1h); SYM(__nv_bfloat16, wd1l, g_wd1l);
    SYM(__nv_bfloat16, wd2h, g_wd2h); SYM(__nv_bfloat16, wd2l, g_wd2l);
    SYM(__nv_bfloat16, wd3h, g_wd3h); SYM(__nv_bfloat16, wd3l, g_wd3l);
#undef SYM

    zero_stats_kernel<<<1, 32>>>();

    {
        CvtArgs a;
        unsigned base = 0;
        auto set = [&](int i, const float* src, __nv_bfloat16* dh, __nv_bfloat16* dl,
                       int rows, int K) {
            a.seg[i] = {src, dh, dl, K, base};
            base += (unsigned)(rows * K / 8);
        };
        set(0, x,   xh,   xl,   N_ROWS, DIM);
        set(1, We1, we1h, we1l, H1,  DIM);
        set(2, We2, we2h, we2l, H2,  H1);
        set(3, We3, we3h, we3l, LAT, H2);
        set(4, Wd1, wd1h, wd1l, H2,  LAT);
        set(5, Wd2, wd2h, wd2l, H1,  H2);
        set(6, Wd3, wd3h, wd3l, DIM, H1);
        a.total = base;
        convert_all_kernel<<<(base + 255) / 256, 256>>>(a);
    }
    rownorm_kernel<<<N_ROWS, 256>>>(x, rx, DIM);

    const int smem_gemm = GS * 65536 + 1024;
    const int smem_dist = DS * 32768 + 1024;
    cudaFuncSetAttribute(tc_gemm_bias_lrelu, cudaFuncAttributeMaxDynamicSharedMemorySize, smem_gemm);
    cudaFuncSetAttribute(dist_stats_tc_kernel, cudaFuncAttributeMaxDynamicSharedMemorySize, smem_dist);

#define TCL(ah_, al_, wh_, wl_, b_, c_, oh_, ol_, N_, K_, wf, ws) \
    tc_gemm_bias_lrelu<<<dim3((N_) / 128, NB), 256, smem_gemm>>>( \
        ah_, al_, wh_, wl_, b_, c_, oh_, ol_, N_, (K_) / 64, wf, ws)
    TCL(xh,  xl,  we1h, we1l, be1, (float*)nullptr, a1h, a1l, H1,  DIM, 0, 1);
    TCL(a1h, a1l, we2h, we2l, be2, (float*)nullptr, a2h, a2l, H2,  H1,  0, 1);
    TCL(a2h, a2l, we3h, we3l, be3, lat,             lh,  ll,  LAT, H2,  1, 1);
    rownorm_kernel<<<N_ROWS, 128>>>(lat, rl, LAT);
    TCL(lh,  ll,  wd1h, wd1l, bd1, (float*)nullptr, a4h, a4l, H2,  LAT, 0, 1);
    TCL(a4h, a4l, wd2h, wd2l, bd2, (float*)nullptr, a5h, a5l, H1,  H2,  0, 1);
    TCL(a5h, a5l, wd3h, wd3l, bd3, out,  (__nv_bfloat16*)nullptr, (__nv_bfloat16*)nullptr, DIM, H1, 1, 0);
#undef TCL

    dist_stats_tc_kernel<<<NB * (NB + 1) / 2, 256, smem_dist>>>(xh, lh, rx, rl);

    finalize_kernel<<<1, 1>>>(out, (long long)out_size - 1);
}